// round 11
// baseline (speedup 1.0000x reference)
#include <cuda_runtime.h>
#include <cuda_fp16.h>
#include <math.h>
#include <stdint.h>

#define BB 2
#define LL 2048
#define DD 1024
#define NH 16
#define NKV 4
#define HD 64
#define WIN 1024
#define QKV_DIM 1536
#define EPSV 1.1920929e-07f

// ---------------- scratch (no cudaMalloc allowed) ----------------
__device__ __half g_hh[BB * LL * DD];
__device__ __half g_wqkvh[QKV_DIM * DD];
__device__ __half g_wouth[DD * DD];
__device__ __half g_yh[BB * LL * DD];
__device__ __half g_qh[BB * NH * LL * HD];
__device__ __half g_kh[BB * NKV * LL * HD];
__device__ __half g_vh[BB * NKV * LL * HD];
__device__ int    g_lo[BB * LL];
__device__ float4 g_rope[LL * 16];

// ---------------- ptx helpers ----------------
__device__ __forceinline__ uint32_t smem_u32(const void* p) {
    uint32_t a;
    asm("{ .reg .u64 t; cvta.to.shared.u64 t, %1; cvt.u32.u64 %0, t; }"
        : "=r"(a) : "l"(p));
    return a;
}
__device__ __forceinline__ void cp16(uint32_t smem_dst, const void* gsrc) {
    asm volatile("cp.async.cg.shared.global [%0], [%1], 16;\n"
                 :: "r"(smem_dst), "l"(gsrc));
}
__device__ __forceinline__ void cp_commit() {
    asm volatile("cp.async.commit_group;\n");
}
template <int N>
__device__ __forceinline__ void cp_wait() {
    asm volatile("cp.async.wait_group %0;\n" :: "n"(N));
}
__device__ __forceinline__ void ldsm4(uint32_t* r, uint32_t addr) {
    asm volatile("ldmatrix.sync.aligned.m8n8.x4.shared.b16 {%0,%1,%2,%3}, [%4];"
                 : "=r"(r[0]), "=r"(r[1]), "=r"(r[2]), "=r"(r[3]) : "r"(addr));
}
__device__ __forceinline__ void ldsm4t(uint32_t* r, uint32_t addr) {
    asm volatile("ldmatrix.sync.aligned.m8n8.x4.trans.shared.b16 {%0,%1,%2,%3}, [%4];"
                 : "=r"(r[0]), "=r"(r[1]), "=r"(r[2]), "=r"(r[3]) : "r"(addr));
}
__device__ __forceinline__ void mma_f16(float* c, const uint32_t* a, const uint32_t* b) {
    asm volatile(
        "mma.sync.aligned.m16n8k16.row.col.f32.f16.f16.f32 "
        "{%0,%1,%2,%3}, {%4,%5,%6,%7}, {%8,%9}, {%0,%1,%2,%3};"
        : "+f"(c[0]), "+f"(c[1]), "+f"(c[2]), "+f"(c[3])
        : "r"(a[0]), "r"(a[1]), "r"(a[2]), "r"(a[3]), "r"(b[0]), "r"(b[1]));
}

// ---------------- fused prep kernel ----------------
#define NB_SEG  BB
#define NB_ROPE 128
#define NB_CONV 2560
#define NB_RMS  (BB * LL)
#define NB_TOT  (NB_SEG + NB_ROPE + NB_CONV + NB_RMS)

__global__ void __launch_bounds__(256) prep_kernel(
    const float* __restrict__ x, const float* __restrict__ wq,
    const float* __restrict__ wo, const void* __restrict__ mask)
{
    const int bid = blockIdx.x;
    const int t = threadIdx.x;

    if (bid < NB_SEG) {
        __shared__ int sA[256];
        __shared__ int sB[256];
        __shared__ int encs;
        const int b = bid;
        if (t == 0) {
            const unsigned* mi = (const unsigned*)mask;
            int e = 0;
            for (int i = 0; i < 64; i++) {
                unsigned v = mi[i];
                if (v == 0x3F800000u) { e = 2; break; }
                if (v > 1u) e = 1;
            }
            encs = e;
        }
        __syncthreads();
        const int e = encs;

        int pref[8];
        int run = 0;
        const int base = t * 8;
#pragma unroll
        for (int i = 0; i < 8; i++) {
            const int idx = base + i;
            int mset;
            if (e == 0)      mset = ((const int*)mask)[b * LL + idx] != 0;
            else if (e == 1) mset = ((const unsigned char*)mask)[b * LL + idx] != 0;
            else             mset = ((const float*)mask)[b * LL + idx] != 0.0f;
            run = max(run, mset ? idx : 0);
            pref[i] = run;
        }
        sA[t] = run;
        __syncthreads();
        int* s = sA;
        int* d = sB;
        for (int off = 1; off < 256; off <<= 1) {
            int v = s[t];
            if (t >= off) v = max(v, s[t - off]);
            d[t] = v;
            __syncthreads();
            int* tmp = s; s = d; d = tmp;
        }
        const int excl = (t > 0) ? s[t - 1] : 0;
#pragma unroll
        for (int i = 0; i < 8; i++) {
            const int idx = base + i;
            g_lo[b * LL + idx] = max(idx - (WIN - 1), max(excl, pref[i]));
        }
    } else if (bid < NB_SEG + NB_ROPE) {
        const int i = (bid - NB_SEG) * 256 + t;
        const int l = i >> 4;
        const int j = (i & 15) * 2;
        const float lg = logf(10000.0f) * (1.0f / 32.0f);
        const float f0 = expf(-lg * (float)j);
        const float f1 = expf(-lg * (float)(j + 1));
        float s0, c0, s1, c1;
        sincosf((float)l * f0, &s0, &c0);
        sincosf((float)l * f1, &s1, &c1);
        g_rope[i] = make_float4(c0, c1, s0, s1);
    } else if (bid < NB_SEG + NB_ROPE + NB_CONV) {
        const int n1 = QKV_DIM * DD;
        const int i = ((bid - NB_SEG - NB_ROPE) * 256 + t) * 4;
        if (i < n1) {
            float4 v = *(const float4*)(wq + i);
            *(__half2*)(g_wqkvh + i) = __floats2half2_rn(v.x, v.y);
            *(__half2*)(g_wqkvh + i + 2) = __floats2half2_rn(v.z, v.w);
        } else {
            const int k = i - n1;
            float4 v = *(const float4*)(wo + k);
            *(__half2*)(g_wouth + k) = __floats2half2_rn(v.x, v.y);
            *(__half2*)(g_wouth + k + 2) = __floats2half2_rn(v.z, v.w);
        }
    } else {
        const int row = bid - (NB_SEG + NB_ROPE + NB_CONV);
        const float4* xr = (const float4*)(x + (size_t)row * DD);
        __half2* hr = (__half2*)(g_hh + (size_t)row * DD);
        const float4 v = xr[t];
        float ss = v.x * v.x + v.y * v.y + v.z * v.z + v.w * v.w;

        __shared__ float red[8];
#pragma unroll
        for (int m = 16; m; m >>= 1) ss += __shfl_xor_sync(0xffffffffu, ss, m);
        if ((t & 31) == 0) red[t >> 5] = ss;
        __syncthreads();
        if (t < 8) {
            float r = red[t];
#pragma unroll
            for (int m = 4; m; m >>= 1) r += __shfl_xor_sync(0xffu, r, m, 8);
            if (t == 0) red[0] = r;
        }
        __syncthreads();
        const float inv = rsqrtf(red[0] * (1.0f / DD) + EPSV);
        hr[t * 2] = __floats2half2_rn(v.x * inv, v.y * inv);
        hr[t * 2 + 1] = __floats2half2_rn(v.z * inv, v.w * inv);
    }
}

// ---------------- fp16 mma.sync GEMM: 256 threads, 8 warps, 2 CTAs/SM ----------------
// 128x128 tile, BK=64, NSTG=2 (68KB smem -> 2 CTAs/SM). Warp tile 32x64 (4m x 2n).
// Fragment double-buffered within chunk. EPI=1: C=A@W^T+res. EPI=2: fused qkv.
#define NSTG 2
#define STG_B (128 * 128)
#define GSMEM 69632

template <int EPI>
__global__ void __launch_bounds__(256, 2) hgemm_kernel(
    const __half* __restrict__ A, const __half* __restrict__ W,
    const float* __restrict__ res, float* __restrict__ C,
    int M, int N, int K)
{
    extern __shared__ char smem[];
    const uint32_t sb = smem_u32(smem);
    const uint32_t Asm = sb;
    const uint32_t Bsm = sb + NSTG * STG_B;

    const int t = threadIdx.x;
    const int lane = t & 31;
    const int wid = t >> 5;               // 0..7
    const int wm = (wid & 3) * 32;        // 4 m-warps
    const int wn = (wid >> 2) * 64;       // 2 n-warps
    const int m0 = blockIdx.y * 128;
    const int n0 = blockIdx.x * 128;

    // loader: thread -> row t/2, 4 x 16B chunks at (t&1)*64 per operand
    const int lrow = t >> 1;
    const int lcb0 = (t & 1) * 64;
    const int lswz = (lrow & 7) << 4;
    const char* Agb = (const char*)(A + (size_t)(m0 + lrow) * K);
    const char* Wgb = (const char*)(W + (size_t)(n0 + lrow) * K);
    const uint32_t arow = Asm + lrow * 128;
    const uint32_t brow = Bsm + lrow * 128;

    float acc[2][8][4];
#pragma unroll
    for (int i = 0; i < 2; i++)
#pragma unroll
        for (int j = 0; j < 8; j++)
#pragma unroll
            for (int r = 0; r < 4; r++) acc[i][j][r] = 0.f;

    const int grp = lane >> 3;
    const int li = lane & 7;
    uint32_t a_ro[2]; int a_sw[2];
    uint32_t b_ro[4]; int b_sw[4];
#pragma unroll
    for (int mi = 0; mi < 2; mi++) {
        const int r = wm + mi * 16 + li + (grp & 1) * 8;
        a_ro[mi] = r * 128;
        a_sw[mi] = (r & 7) << 4;
    }
#pragma unroll
    for (int nb = 0; nb < 4; nb++) {
        const int r = wn + nb * 16 + li + (grp >> 1) * 8;
        b_ro[nb] = r * 128;
        b_sw[nb] = (r & 7) << 4;
    }
    const int a_g16 = (grp >> 1) * 16;
    const int b_g16 = (grp & 1) * 16;

    const int nch = K >> 6;

    // preload chunk 0 into stage 0
#pragma unroll
    for (int i = 0; i < 4; i++) {
        const int cb = lcb0 + i * 16;
        cp16(arow + (cb ^ lswz), Agb + cb);
        cp16(brow + (cb ^ lswz), Wgb + cb);
    }
    cp_commit();

    uint32_t af[2][2][4], bf[2][4][4];

    for (int c = 0; c < nch; c++) {
        cp_wait<0>();
        __syncthreads();

        // prefetch chunk c+1 into the other stage (overlaps compute of c)
        if (c + 1 < nch) {
            const int s = (c + 1) & 1;
#pragma unroll
            for (int i = 0; i < 4; i++) {
                const int cb = lcb0 + i * 16;
                cp16(arow + s * STG_B + (cb ^ lswz), Agb + (size_t)(c + 1) * 128 + cb);
                cp16(brow + s * STG_B + (cb ^ lswz), Wgb + (size_t)(c + 1) * 128 + cb);
            }
            cp_commit();
        }

        const uint32_t as = Asm + (c & 1) * STG_B;
        const uint32_t bs = Bsm + (c & 1) * STG_B;

        // ks0 fragments
#pragma unroll
        for (int mi = 0; mi < 2; mi++)
            ldsm4(af[0][mi], as + a_ro[mi] + (a_g16 ^ a_sw[mi]));
#pragma unroll
        for (int nb = 0; nb < 4; nb++)
            ldsm4(bf[0][nb], bs + b_ro[nb] + (b_g16 ^ b_sw[nb]));

        int buf = 0;
#pragma unroll
        for (int ks = 0; ks < 4; ks++) {
            if (ks < 3) {
                const int koff = (ks + 1) * 32;
#pragma unroll
                for (int mi = 0; mi < 2; mi++)
                    ldsm4(af[buf ^ 1][mi], as + a_ro[mi] + ((koff + a_g16) ^ a_sw[mi]));
#pragma unroll
                for (int nb = 0; nb < 4; nb++)
                    ldsm4(bf[buf ^ 1][nb], bs + b_ro[nb] + ((koff + b_g16) ^ b_sw[nb]));
            }
#pragma unroll
            for (int mi = 0; mi < 2; mi++)
#pragma unroll
                for (int ni = 0; ni < 8; ni++)
                    mma_f16(acc[mi][ni], af[buf][mi], &bf[buf][ni >> 1][(ni & 1) * 2]);
            buf ^= 1;
        }
        __syncthreads();  // frags of chunk c read; safe for c+2's cp next iter
    }

    const int g = lane >> 2;
    const int tg = lane & 3;

    if (EPI == 1) {
#pragma unroll
        for (int mi = 0; mi < 2; mi++) {
#pragma unroll
            for (int ni = 0; ni < 8; ni++) {
                const int row = m0 + wm + mi * 16 + g;
                const int col = n0 + wn + ni * 8 + tg * 2;
                float2 v0 = make_float2(acc[mi][ni][0], acc[mi][ni][1]);
                float2 v1 = make_float2(acc[mi][ni][2], acc[mi][ni][3]);
                const float2 r0 = *(const float2*)(res + (size_t)row * N + col);
                const float2 r1 = *(const float2*)(res + (size_t)(row + 8) * N + col);
                v0.x += r0.x; v0.y += r0.y;
                v1.x += r1.x; v1.y += r1.y;
                *(float2*)(C + (size_t)row * N + col) = v0;
                *(float2*)(C + (size_t)(row + 8) * N + col) = v1;
            }
        }
    } else {
        // ---- fused qkv epilogue: stage tile to smem, per-head norm+rope ----
        __syncthreads();
        float* sf = (float*)smem;  // [128][132] = 67584 B (fits GSMEM)
#pragma unroll
        for (int mi = 0; mi < 2; mi++) {
#pragma unroll
            for (int ni = 0; ni < 8; ni++) {
                const int r = wm + mi * 16 + g;
                const int cl = wn + ni * 8 + tg * 2;
                *(float2*)&sf[r * 132 + cl] = make_float2(acc[mi][ni][0], acc[mi][ni][1]);
                *(float2*)&sf[(r + 8) * 132 + cl] = make_float2(acc[mi][ni][2], acc[mi][ni][3]);
            }
        }
        __syncthreads();

        const int gi = t >> 4;        // 0..15
        const int tl = t & 15;
        const int j = tl * 2;
        const int hbase = n0 >> 6;

        for (int it = 0; it < 16; it++) {
            const int p = it * 16 + gi;
            const int r = p >> 1;
            const int hh = p & 1;
            const int head = hbase + hh;
            const int rowg = m0 + r;
            const int b = rowg >> 11;
            const int l = rowg & (LL - 1);
            const float* sr = &sf[r * 132 + hh * 64];

            const float a0 = sr[j], a1 = sr[j + 1];
            const float b0 = sr[j + 32], b1 = sr[j + 33];

            if (head < 20) {
                float ss = a0 * a0 + a1 * a1 + b0 * b0 + b1 * b1;
#pragma unroll
                for (int m = 8; m; m >>= 1)
                    ss += __shfl_xor_sync(0xffffffffu, ss, m, 16);
                const float inv = rsqrtf(ss * (1.0f / HD) + EPSV);
                const float4 rp = g_rope[l * 16 + tl];
                const float a0n = a0 * inv, a1n = a1 * inv;
                const float b0n = b0 * inv, b1n = b1 * inv;
                const float o0 = a0n * rp.x - b0n * rp.z;
                const float o1 = a1n * rp.y - b1n * rp.w;
                const float o2 = a0n * rp.z + b0n * rp.x;
                const float o3 = a1n * rp.w + b1n * rp.y;
                if (head < 16) {
                    const float sc = 0.125f;
                    __half* dq = g_qh + (((size_t)(b * NH + head)) * LL + l) * HD;
                    *(__half2*)(dq + j) = __floats2half2_rn(o0 * sc, o1 * sc);
                    *(__half2*)(dq + j + 32) = __floats2half2_rn(o2 * sc, o3 * sc);
                } else {
                    __half* dk = g_kh + (((size_t)(b * NKV + (head - 16))) * LL + l) * HD;
                    *(__half2*)(dk + j) = __floats2half2_rn(o0, o1);
                    *(__half2*)(dk + j + 32) = __floats2half2_rn(o2, o3);
                }
            } else {
                __half* dv = g_vh + (((size_t)(b * NKV + (head - 20))) * LL + l) * HD;
                *(__half2*)(dv + j) = __floats2half2_rn(a0, a1);
                *(__half2*)(dv + j + 32) = __floats2half2_rn(b0, b1);
            }
        }
    }
}

// ---------------- tensor-core flash attention ----------------
#define ATT_SMEM (5 * 8192)
__global__ void __launch_bounds__(128) attn_mma_kernel() {
    extern __shared__ char smc[];
    const uint32_t sb = smem_u32(smc);
    const uint32_t Qs = sb;
    const uint32_t Ks = sb + 8192;
    const uint32_t Vs = sb + 3 * 8192;
    __shared__ int lo_s[64];

    const int qb = blockIdx.x, h = blockIdx.y, b = blockIdx.z;
    const int t = threadIdx.x;
    const int lane = t & 31;
    const int w = t >> 5;
    const int q0 = qb * 64;
    const int kvh = h >> 2;
    const char* Qg = (const char*)(g_qh + (((size_t)(b * NH + h)) * LL + q0) * HD);
    const char* Kg = (const char*)(g_kh + ((size_t)(b * NKV + kvh)) * LL * HD);
    const char* Vg = (const char*)(g_vh + ((size_t)(b * NKV + kvh)) * LL * HD);

    const int kb0 = g_lo[b * LL + q0] & ~63;
    const int nt = ((q0 + 63 - kb0) >> 6) + 1;
    if (t < 64) lo_s[t] = g_lo[b * LL + q0 + t];

    const int lrow = t >> 1;
    const int lcb0 = (t & 1) * 64;
    const int lswz = (lrow & 7) << 4;
    const uint32_t qrow_s = Qs + lrow * 128;
    const uint32_t krow_s = Ks + lrow * 128;
    const uint32_t vrow_s = Vs + lrow * 128;

#pragma unroll
    for (int i = 0; i < 4; i++) {
        const int cb = lcb0 + i * 16;
        cp16(qrow_s + (cb ^ lswz), Qg + lrow * 128 + cb);
        cp16(krow_s + (cb ^ lswz), Kg + (size_t)(kb0 + lrow) * 128 + cb);
        cp16(vrow_s + (cb ^ lswz), Vg + (size_t)(kb0 + lrow) * 128 + cb);
    }
    cp_commit();

    const int grp = lane >> 3;
    const int li = lane & 7;
    const int g = lane >> 2;
    const int tg = lane & 3;
    const int row0 = w * 16 + g;
    const int qg0 = q0 + row0;
    const int qg1 = qg0 + 8;

    cp_wait<0>();
    __syncthreads();

    uint32_t aQ[4][4];
    {
        const int qr = w * 16 + li + (grp & 1) * 8;
        const uint32_t qa = Qs + qr * 128;
        const int qsw = (qr & 7) << 4;
        const int qg16 = (grp >> 1) * 16;
#pragma unroll
        for (int kk = 0; kk < 4; kk++)
            ldsm4(aQ[kk], qa + ((kk * 32 + qg16) ^ qsw));
    }

    const int lo0 = lo_s[row0];
    const int lo1 = lo_s[row0 + 8];

    uint32_t k_ro[4]; int k_sw[4];
    uint32_t v_co[4];
#pragma unroll
    for (int nb = 0; nb < 4; nb++) {
        const int r = nb * 16 + li + (grp >> 1) * 8;
        k_ro[nb] = r * 128;
        k_sw[nb] = (r & 7) << 4;
        v_co[nb] = nb * 32 + (grp >> 1) * 16;
    }
    const int k_g16 = (grp & 1) * 16;
    const int v_r8 = (grp & 1) * 8 + li;

    float m0 = -1e30f, m1 = -1e30f, l0 = 0.f, l1 = 0.f;
    float o[8][4];
#pragma unroll
    for (int jn = 0; jn < 8; jn++)
#pragma unroll
        for (int r = 0; r < 4; r++) o[jn][r] = 0.f;

    for (int i = 0; i < nt; i++) {
        const int kb = kb0 + i * 64;
        if (i + 1 < nt) {
            const int bo = ((i + 1) & 1) * 8192;
            const size_t go = (size_t)(kb + 64 + lrow) * 128;
#pragma unroll
            for (int c2 = 0; c2 < 4; c2++) {
                const int cb = lcb0 + c2 * 16;
                cp16(krow_s + bo + (cb ^ lswz), Kg + go + cb);
                cp16(vrow_s + bo + (cb ^ lswz), Vg + go + cb);
            }
        }
        cp_commit();
        cp_wait<1>();
        __syncthreads();

        const uint32_t Kb = Ks + (i & 1) * 8192;
        const uint32_t Vb = Vs + (i & 1) * 8192;

        float sc[8][4];
#pragma unroll
        for (int j = 0; j < 8; j++)
#pragma unroll
            for (int r = 0; r < 4; r++) sc[j][r] = 0.f;

#pragma unroll
        for (int kk = 0; kk < 4; kk++) {
            uint32_t bfr[4][4];
#pragma unroll
            for (int nb = 0; nb < 4; nb++)
                ldsm4(bfr[nb], Kb + k_ro[nb] + ((kk * 32 + k_g16) ^ k_sw[nb]));
#pragma unroll
            for (int j = 0; j < 8; j++)
                mma_f16(sc[j], aQ[kk], &bfr[j >> 1][(j & 1) * 2]);
        }

        float mx0 = -1e30f, mx1 = -1e30f;
#pragma unroll
        for (int j = 0; j < 8; j++) {
            const int c0 = kb + j * 8 + tg * 2;
            const int c1 = c0 + 1;
            if (c0 < lo0 || c0 > qg0) sc[j][0] = -1e30f;
            if (c1 < lo0 || c1 > qg0) sc[j][1] = -1e30f;
            if (c0 < lo1 || c0 > qg1) sc[j][2] = -1e30f;
            if (c1 < lo1 || c1 > qg1) sc[j][3] = -1e30f;
            mx0 = fmaxf(mx0, fmaxf(sc[j][0], sc[j][1]));
            mx1 = fmaxf(mx1, fmaxf(sc[j][2], sc[j][3]));
        }
        mx0 = fmaxf(mx0, __shfl_xor_sync(0xffffffffu, mx0, 1));
        mx0 = fmaxf(mx0, __shfl_xor_sync(0xffffffffu, mx0, 2));
        mx1 = fmaxf(mx1, __shfl_xor_sync(0xffffffffu, mx1, 1));
        mx1 = fmaxf(mx1, __shfl_xor_sync(0xffffffffu, mx1, 2));

        const float mn0 = fmaxf(m0, mx0);
        const float mn1 = fmaxf(m1, mx1);
        const float al0 = __expf(m0 - mn0);
        const float al1 = __expf(m1 - mn1);

        float lp0 = 0.f, lp1 = 0.f;
        uint32_t ph[8][2];
#pragma unroll
        for (int j = 0; j < 8; j++) {
            const float p0 = (sc[j][0] > -1e29f) ? __expf(sc[j][0] - mn0) : 0.f;
            const float p1 = (sc[j][1] > -1e29f) ? __expf(sc[j][1] - mn0) : 0.f;
            const float p2 = (sc[j][2] > -1e29f) ? __expf(sc[j][2] - mn1) : 0.f;
            const float p3 = (sc[j][3] > -1e29f) ? __expf(sc[j][3] - mn1) : 0.f;
            lp0 += p0 + p1;
            lp1 += p2 + p3;
            __half2 h0 = __floats2half2_rn(p0, p1);
            __half2 h1 = __floats2half2_rn(p2, p3);
            ph[j][0] = *(uint32_t*)&h0;
            ph[j][1] = *(uint32_t*)&h1;
        }
        lp0 += __shfl_xor_sync(0xffffffffu, lp0, 1);
        lp0 += __shfl_xor_sync(0xffffffffu, lp0, 2);
        lp1 += __shfl_xor_sync(0xffffffffu, lp1, 1);
        lp1 += __shfl_xor_sync(0xffffffffu, lp1, 2);

        l0 = l0 * al0 + lp0;
        l1 = l1 * al1 + lp1;
        m0 = mn0; m1 = mn1;
#pragma unroll
        for (int jn = 0; jn < 8; jn++) {
            o[jn][0] *= al0; o[jn][1] *= al0;
            o[jn][2] *= al1; o[jn][3] *= al1;
        }

#pragma unroll
        for (int kk = 0; kk < 4; kk++) {
            uint32_t vf[4][4];
            const int vr = kk * 16 + v_r8;
            const uint32_t va = Vb + vr * 128;
            const int vsw = (vr & 7) << 4;
#pragma unroll
            for (int nb = 0; nb < 4; nb++)
                ldsm4t(vf[nb], va + (v_co[nb] ^ vsw));
            uint32_t aP[4] = { ph[2 * kk][0], ph[2 * kk][1],
                               ph[2 * kk + 1][0], ph[2 * kk + 1][1] };
#pragma unroll
            for (int jn = 0; jn < 8; jn++)
                mma_f16(o[jn], aP, &vf[jn >> 1][(jn & 1) * 2]);
        }
        __syncthreads();
    }

    const float iv0 = 1.0f / l0;
    const float iv1 = 1.0f / l1;
    __half* y0 = g_yh + ((size_t)(b * LL) + qg0) * DD + h * HD;
    __half* y1 = g_yh + ((size_t)(b * LL) + qg1) * DD + h * HD;
#pragma unroll
    for (int jn = 0; jn < 8; jn++) {
        __half2 r0 = __floats2half2_rn(o[jn][0] * iv0, o[jn][1] * iv0);
        __half2 r1 = __floats2half2_rn(o[jn][2] * iv1, o[jn][3] * iv1);
        *(__half2*)(y0 + jn * 8 + tg * 2) = r0;
        *(__half2*)(y1 + jn * 8 + tg * 2) = r1;
    }
}

// ---------------- launch ----------------
extern "C" void kernel_launch(void* const* d_in, const int* in_sizes, int n_in,
                              void* d_out, int out_size) {
    const float* x     = (const float*)d_in[0];
    const float* w_qkv = (const float*)d_in[1];
    const float* w_out = (const float*)d_in[2];
    const void*  mask  = d_in[3];
    float* out = (float*)d_out;

    __half *phh, *pwqh, *pwoh, *pyh;
    cudaGetSymbolAddress((void**)&phh, g_hh);
    cudaGetSymbolAddress((void**)&pwqh, g_wqkvh);
    cudaGetSymbolAddress((void**)&pwoh, g_wouth);
    cudaGetSymbolAddress((void**)&pyh, g_yh);

    const int M = BB * LL;

    cudaFuncSetAttribute(hgemm_kernel<1>,
                         cudaFuncAttributeMaxDynamicSharedMemorySize, GSMEM);
    cudaFuncSetAttribute(hgemm_kernel<2>,
                         cudaFuncAttributeMaxDynamicSharedMemorySize, GSMEM);
    cudaFuncSetAttribute(attn_mma_kernel,
                         cudaFuncAttributeMaxDynamicSharedMemorySize, ATT_SMEM);

    prep_kernel<<<NB_TOT, 256>>>(x, w_qkv, w_out, mask);

    hgemm_kernel<2><<<dim3(QKV_DIM / 128, M / 128), 256, GSMEM>>>(
        phh, pwqh, nullptr, nullptr, M, QKV_DIM, DD);

    attn_mma_kernel<<<dim3(LL / 64, NH, BB), 128, ATT_SMEM>>>();

    hgemm_kernel<1><<<dim3(DD / 128, M / 128), 256, GSMEM>>>(
        pyh, pwoh, x, out, M, DD, DD);
}

// round 12
// speedup vs baseline: 1.0383x; 1.0383x over previous
#include <cuda_runtime.h>
#include <cuda_fp16.h>
#include <math.h>
#include <stdint.h>

#define BB 2
#define LL 2048
#define DD 1024
#define NH 16
#define NKV 4
#define HD 64
#define WIN 1024
#define QKV_DIM 1536
#define EPSV 1.1920929e-07f

// ---------------- scratch (no cudaMalloc allowed) ----------------
__device__ __half g_hh[BB * LL * DD];
__device__ __half g_wqkvh[QKV_DIM * DD];
__device__ __half g_wouth[DD * DD];
__device__ __half g_yh[BB * LL * DD];
__device__ __half g_qh[BB * NH * LL * HD];
__device__ __half g_kh[BB * NKV * LL * HD];
__device__ __half g_vh[BB * NKV * LL * HD];
__device__ int    g_lo[BB * LL];
__device__ float4 g_rope[LL * 16];

// ---------------- ptx helpers ----------------
__device__ __forceinline__ uint32_t smem_u32(const void* p) {
    uint32_t a;
    asm("{ .reg .u64 t; cvta.to.shared.u64 t, %1; cvt.u32.u64 %0, t; }"
        : "=r"(a) : "l"(p));
    return a;
}
__device__ __forceinline__ void cp16(uint32_t smem_dst, const void* gsrc) {
    asm volatile("cp.async.cg.shared.global [%0], [%1], 16;\n"
                 :: "r"(smem_dst), "l"(gsrc));
}
__device__ __forceinline__ void cp_commit() {
    asm volatile("cp.async.commit_group;\n");
}
template <int N>
__device__ __forceinline__ void cp_wait() {
    asm volatile("cp.async.wait_group %0;\n" :: "n"(N));
}
__device__ __forceinline__ void ldsm4(uint32_t* r, uint32_t addr) {
    asm volatile("ldmatrix.sync.aligned.m8n8.x4.shared.b16 {%0,%1,%2,%3}, [%4];"
                 : "=r"(r[0]), "=r"(r[1]), "=r"(r[2]), "=r"(r[3]) : "r"(addr));
}
__device__ __forceinline__ void ldsm4t(uint32_t* r, uint32_t addr) {
    asm volatile("ldmatrix.sync.aligned.m8n8.x4.trans.shared.b16 {%0,%1,%2,%3}, [%4];"
                 : "=r"(r[0]), "=r"(r[1]), "=r"(r[2]), "=r"(r[3]) : "r"(addr));
}
__device__ __forceinline__ void mma_f16(float* c, const uint32_t* a, const uint32_t* b) {
    asm volatile(
        "mma.sync.aligned.m16n8k16.row.col.f32.f16.f16.f32 "
        "{%0,%1,%2,%3}, {%4,%5,%6,%7}, {%8,%9}, {%0,%1,%2,%3};"
        : "+f"(c[0]), "+f"(c[1]), "+f"(c[2]), "+f"(c[3])
        : "r"(a[0]), "r"(a[1]), "r"(a[2]), "r"(a[3]), "r"(b[0]), "r"(b[1]));
}

// ---------------- fused prep kernel ----------------
#define NB_SEG  BB
#define NB_ROPE 128
#define NB_CONV 2560
#define NB_RMS  (BB * LL)
#define NB_TOT  (NB_SEG + NB_ROPE + NB_CONV + NB_RMS)

__global__ void __launch_bounds__(256) prep_kernel(
    const float* __restrict__ x, const float* __restrict__ wq,
    const float* __restrict__ wo, const void* __restrict__ mask)
{
    const int bid = blockIdx.x;
    const int t = threadIdx.x;

    if (bid < NB_SEG) {
        __shared__ int sA[256];
        __shared__ int sB[256];
        __shared__ int encs;
        const int b = bid;
        if (t == 0) {
            const unsigned* mi = (const unsigned*)mask;
            int e = 0;
            for (int i = 0; i < 64; i++) {
                unsigned v = mi[i];
                if (v == 0x3F800000u) { e = 2; break; }
                if (v > 1u) e = 1;
            }
            encs = e;
        }
        __syncthreads();
        const int e = encs;

        int pref[8];
        int run = 0;
        const int base = t * 8;
#pragma unroll
        for (int i = 0; i < 8; i++) {
            const int idx = base + i;
            int mset;
            if (e == 0)      mset = ((const int*)mask)[b * LL + idx] != 0;
            else if (e == 1) mset = ((const unsigned char*)mask)[b * LL + idx] != 0;
            else             mset = ((const float*)mask)[b * LL + idx] != 0.0f;
            run = max(run, mset ? idx : 0);
            pref[i] = run;
        }
        sA[t] = run;
        __syncthreads();
        int* s = sA;
        int* d = sB;
        for (int off = 1; off < 256; off <<= 1) {
            int v = s[t];
            if (t >= off) v = max(v, s[t - off]);
            d[t] = v;
            __syncthreads();
            int* tmp = s; s = d; d = tmp;
        }
        const int excl = (t > 0) ? s[t - 1] : 0;
#pragma unroll
        for (int i = 0; i < 8; i++) {
            const int idx = base + i;
            g_lo[b * LL + idx] = max(idx - (WIN - 1), max(excl, pref[i]));
        }
    } else if (bid < NB_SEG + NB_ROPE) {
        const int i = (bid - NB_SEG) * 256 + t;
        const int l = i >> 4;
        const int j = (i & 15) * 2;
        const float lg = logf(10000.0f) * (1.0f / 32.0f);
        const float f0 = expf(-lg * (float)j);
        const float f1 = expf(-lg * (float)(j + 1));
        float s0, c0, s1, c1;
        sincosf((float)l * f0, &s0, &c0);
        sincosf((float)l * f1, &s1, &c1);
        g_rope[i] = make_float4(c0, c1, s0, s1);
    } else if (bid < NB_SEG + NB_ROPE + NB_CONV) {
        const int n1 = QKV_DIM * DD;
        const int i = ((bid - NB_SEG - NB_ROPE) * 256 + t) * 4;
        if (i < n1) {
            float4 v = *(const float4*)(wq + i);
            *(__half2*)(g_wqkvh + i) = __floats2half2_rn(v.x, v.y);
            *(__half2*)(g_wqkvh + i + 2) = __floats2half2_rn(v.z, v.w);
        } else {
            const int k = i - n1;
            float4 v = *(const float4*)(wo + k);
            *(__half2*)(g_wouth + k) = __floats2half2_rn(v.x, v.y);
            *(__half2*)(g_wouth + k + 2) = __floats2half2_rn(v.z, v.w);
        }
    } else {
        const int row = bid - (NB_SEG + NB_ROPE + NB_CONV);
        const float4* xr = (const float4*)(x + (size_t)row * DD);
        __half2* hr = (__half2*)(g_hh + (size_t)row * DD);
        const float4 v = xr[t];
        float ss = v.x * v.x + v.y * v.y + v.z * v.z + v.w * v.w;

        __shared__ float red[8];
#pragma unroll
        for (int m = 16; m; m >>= 1) ss += __shfl_xor_sync(0xffffffffu, ss, m);
        if ((t & 31) == 0) red[t >> 5] = ss;
        __syncthreads();
        if (t < 8) {
            float r = red[t];
#pragma unroll
            for (int m = 4; m; m >>= 1) r += __shfl_xor_sync(0xffu, r, m, 8);
            if (t == 0) red[0] = r;
        }
        __syncthreads();
        const float inv = rsqrtf(red[0] * (1.0f / DD) + EPSV);
        hr[t * 2] = __floats2half2_rn(v.x * inv, v.y * inv);
        hr[t * 2 + 1] = __floats2half2_rn(v.z * inv, v.w * inv);
    }
}

// ---------------- fp16 mma.sync GEMM: 512 threads, 16 warps, BK=128, NSTG=3 ----------------
// 128x128 tile; chunk = 128 k (256B/row), stage 32KB/operand, 192KB smem, 1 CTA/SM.
// Warp tile 32x32 (4m x 4n). Fragment double-buffered; one barrier per 8 ks.
// Swizzle per 128B half: SWZ(x) = ((x & 127) ^ swz) + (x & 128).
#define NSTG 3
#define STG_B (128 * 256)
#define GSMEM (2 * NSTG * STG_B)
#define SWZ(x, sw) ((((x) & 127) ^ (sw)) + ((x) & 128))

template <int EPI>
__global__ void __launch_bounds__(512) hgemm_kernel(
    const __half* __restrict__ A, const __half* __restrict__ W,
    const float* __restrict__ res, float* __restrict__ C,
    int M, int N, int K)
{
    extern __shared__ char smem[];
    const uint32_t sb = smem_u32(smem);
    const uint32_t Asm = sb;
    const uint32_t Bsm = sb + NSTG * STG_B;

    const int t = threadIdx.x;
    const int lane = t & 31;
    const int wid = t >> 5;               // 0..15
    const int wm = (wid & 3) * 32;        // 4 m-warps
    const int wn = (wid >> 2) * 32;       // 4 n-warps
    const int m0 = blockIdx.y * 128;
    const int n0 = blockIdx.x * 128;

    // loader: thread -> row t/4, 4 x 16B chunks at (t&3)*64 within 256B row
    const int lrow = t >> 2;
    const int lcb0 = (t & 3) * 64;
    const int lswz = (lrow & 7) << 4;
    const char* Agb = (const char*)(A + (size_t)(m0 + lrow) * K);
    const char* Wgb = (const char*)(W + (size_t)(n0 + lrow) * K);
    const uint32_t arow = Asm + lrow * 256;
    const uint32_t brow = Bsm + lrow * 256;

    float acc[2][4][4];
#pragma unroll
    for (int i = 0; i < 2; i++)
#pragma unroll
        for (int j = 0; j < 4; j++)
#pragma unroll
            for (int r = 0; r < 4; r++) acc[i][j][r] = 0.f;

    const int grp = lane >> 3;
    const int li = lane & 7;
    uint32_t a_ro[2]; int a_sw[2];
    uint32_t b_ro[2]; int b_sw[2];
#pragma unroll
    for (int mi = 0; mi < 2; mi++) {
        const int r = wm + mi * 16 + li + (grp & 1) * 8;
        a_ro[mi] = r * 256;
        a_sw[mi] = (r & 7) << 4;
    }
#pragma unroll
    for (int nb = 0; nb < 2; nb++) {
        const int r = wn + nb * 16 + li + (grp >> 1) * 8;
        b_ro[nb] = r * 256;
        b_sw[nb] = (r & 7) << 4;
    }
    const int a_g16 = (grp >> 1) * 16;
    const int b_g16 = (grp & 1) * 16;

    const int nch = K >> 7;   // chunks of 128 k

    // preload chunks 0, 1 into stages 0, 1
#pragma unroll
    for (int s = 0; s < NSTG - 1; s++) {
#pragma unroll
        for (int i = 0; i < 4; i++) {
            const int cb = lcb0 + i * 16;
            cp16(arow + s * STG_B + SWZ(cb, lswz), Agb + s * 256 + cb);
            cp16(brow + s * STG_B + SWZ(cb, lswz), Wgb + s * 256 + cb);
        }
        cp_commit();
    }

    cp_wait<NSTG - 2>();
    __syncthreads();

    // fragment double buffers
    uint32_t af[2][2][4], bf[2][2][4];
#pragma unroll
    for (int mi = 0; mi < 2; mi++)
        ldsm4(af[0][mi], Asm + a_ro[mi] + SWZ(a_g16, a_sw[mi]));
#pragma unroll
    for (int nb = 0; nb < 2; nb++)
        ldsm4(bf[0][nb], Bsm + b_ro[nb] + SWZ(b_g16, b_sw[nb]));

    int buf = 0;
    for (int c = 0; c < nch; c++) {
        const uint32_t as = Asm + (c % NSTG) * STG_B;
        const uint32_t bs = Bsm + (c % NSTG) * STG_B;
        const uint32_t asn = Asm + ((c + 1) % NSTG) * STG_B;
        const uint32_t bsn = Bsm + ((c + 1) % NSTG) * STG_B;

#pragma unroll
        for (int ks = 0; ks < 8; ks++) {
            if (ks == 7) {
                // chunk c+1's stage must be landed before loading its frags;
                // barrier also makes iter-c+1's prefetch overwrite safe.
                cp_wait<NSTG - 2>();
                __syncthreads();
            }
            if (c < nch - 1 || ks < 7) {
                const uint32_t las = (ks < 7) ? as : asn;
                const uint32_t lbs = (ks < 7) ? bs : bsn;
                const int koff = ((ks + 1) & 7) * 32;
#pragma unroll
                for (int mi = 0; mi < 2; mi++)
                    ldsm4(af[buf ^ 1][mi], las + a_ro[mi] + SWZ(koff + a_g16, a_sw[mi]));
#pragma unroll
                for (int nb = 0; nb < 2; nb++)
                    ldsm4(bf[buf ^ 1][nb], lbs + b_ro[nb] + SWZ(koff + b_g16, b_sw[nb]));
            }
            if (ks == 0) {
                const int pf = c + NSTG - 1;
                if (pf < nch) {
                    const int s = pf % NSTG;
#pragma unroll
                    for (int i = 0; i < 4; i++) {
                        const int cb = lcb0 + i * 16;
                        cp16(arow + s * STG_B + SWZ(cb, lswz), Agb + (size_t)pf * 256 + cb);
                        cp16(brow + s * STG_B + SWZ(cb, lswz), Wgb + (size_t)pf * 256 + cb);
                    }
                }
                cp_commit();
            }
#pragma unroll
            for (int mi = 0; mi < 2; mi++)
#pragma unroll
                for (int ni = 0; ni < 4; ni++)
                    mma_f16(acc[mi][ni], af[buf][mi], &bf[buf][ni >> 1][(ni & 1) * 2]);
            buf ^= 1;
        }
    }

    const int g = lane >> 2;
    const int tg = lane & 3;

    if (EPI == 1) {
#pragma unroll
        for (int mi = 0; mi < 2; mi++) {
#pragma unroll
            for (int ni = 0; ni < 4; ni++) {
                const int row = m0 + wm + mi * 16 + g;
                const int col = n0 + wn + ni * 8 + tg * 2;
                float2 v0 = make_float2(acc[mi][ni][0], acc[mi][ni][1]);
                float2 v1 = make_float2(acc[mi][ni][2], acc[mi][ni][3]);
                const float2 r0 = *(const float2*)(res + (size_t)row * N + col);
                const float2 r1 = *(const float2*)(res + (size_t)(row + 8) * N + col);
                v0.x += r0.x; v0.y += r0.y;
                v1.x += r1.x; v1.y += r1.y;
                *(float2*)(C + (size_t)row * N + col) = v0;
                *(float2*)(C + (size_t)(row + 8) * N + col) = v1;
            }
        }
    } else {
        // ---- fused qkv epilogue: stage tile to smem, per-head norm+rope ----
        __syncthreads();
        float* sf = (float*)smem;  // [128][132]
#pragma unroll
        for (int mi = 0; mi < 2; mi++) {
#pragma unroll
            for (int ni = 0; ni < 4; ni++) {
                const int r = wm + mi * 16 + g;
                const int cl = wn + ni * 8 + tg * 2;
                *(float2*)&sf[r * 132 + cl] = make_float2(acc[mi][ni][0], acc[mi][ni][1]);
                *(float2*)&sf[(r + 8) * 132 + cl] = make_float2(acc[mi][ni][2], acc[mi][ni][3]);
            }
        }
        __syncthreads();

        const int gi = t >> 4;        // group 0..31
        const int tl = t & 15;
        const int j = tl * 2;
        const int hbase = n0 >> 6;

        for (int it = 0; it < 8; it++) {
            const int p = it * 32 + gi;   // 256 (row, head-in-tile) pairs
            const int r = p >> 1;
            const int hh = p & 1;
            const int head = hbase + hh;
            const int rowg = m0 + r;
            const int b = rowg >> 11;
            const int l = rowg & (LL - 1);
            const float* sr = &sf[r * 132 + hh * 64];

            const float a0 = sr[j], a1 = sr[j + 1];
            const float b0 = sr[j + 32], b1 = sr[j + 33];

            if (head < 20) {
                float ss = a0 * a0 + a1 * a1 + b0 * b0 + b1 * b1;
#pragma unroll
                for (int m = 8; m; m >>= 1)
                    ss += __shfl_xor_sync(0xffffffffu, ss, m, 16);
                const float inv = rsqrtf(ss * (1.0f / HD) + EPSV);
                const float4 rp = g_rope[l * 16 + tl];
                const float a0n = a0 * inv, a1n = a1 * inv;
                const float b0n = b0 * inv, b1n = b1 * inv;
                const float o0 = a0n * rp.x - b0n * rp.z;
                const float o1 = a1n * rp.y - b1n * rp.w;
                const float o2 = a0n * rp.z + b0n * rp.x;
                const float o3 = a1n * rp.w + b1n * rp.y;
                if (head < 16) {
                    const float sc = 0.125f;
                    __half* dq = g_qh + (((size_t)(b * NH + head)) * LL + l) * HD;
                    *(__half2*)(dq + j) = __floats2half2_rn(o0 * sc, o1 * sc);
                    *(__half2*)(dq + j + 32) = __floats2half2_rn(o2 * sc, o3 * sc);
                } else {
                    __half* dk = g_kh + (((size_t)(b * NKV + (head - 16))) * LL + l) * HD;
                    *(__half2*)(dk + j) = __floats2half2_rn(o0, o1);
                    *(__half2*)(dk + j + 32) = __floats2half2_rn(o2, o3);
                }
            } else {
                __half* dv = g_vh + (((size_t)(b * NKV + (head - 20))) * LL + l) * HD;
                *(__half2*)(dv + j) = __floats2half2_rn(a0, a1);
                *(__half2*)(dv + j + 32) = __floats2half2_rn(b0, b1);
            }
        }
    }
}

// ---------------- tensor-core flash attention ----------------
#define ATT_SMEM (5 * 8192)
__global__ void __launch_bounds__(128) attn_mma_kernel() {
    extern __shared__ char smc[];
    const uint32_t sb = smem_u32(smc);
    const uint32_t Qs = sb;
    const uint32_t Ks = sb + 8192;
    const uint32_t Vs = sb + 3 * 8192;
    __shared__ int lo_s[64];

    const int qb = blockIdx.x, h = blockIdx.y, b = blockIdx.z;
    const int t = threadIdx.x;
    const int lane = t & 31;
    const int w = t >> 5;
    const int q0 = qb * 64;
    const int kvh = h >> 2;
    const char* Qg = (const char*)(g_qh + (((size_t)(b * NH + h)) * LL + q0) * HD);
    const char* Kg = (const char*)(g_kh + ((size_t)(b * NKV + kvh)) * LL * HD);
    const char* Vg = (const char*)(g_vh + ((size_t)(b * NKV + kvh)) * LL * HD);

    const int kb0 = g_lo[b * LL + q0] & ~63;
    const int nt = ((q0 + 63 - kb0) >> 6) + 1;
    if (t < 64) lo_s[t] = g_lo[b * LL + q0 + t];

    const int lrow = t >> 1;
    const int lcb0 = (t & 1) * 64;
    const int lswz = (lrow & 7) << 4;
    const uint32_t qrow_s = Qs + lrow * 128;
    const uint32_t krow_s = Ks + lrow * 128;
    const uint32_t vrow_s = Vs + lrow * 128;

#pragma unroll
    for (int i = 0; i < 4; i++) {
        const int cb = lcb0 + i * 16;
        cp16(qrow_s + (cb ^ lswz), Qg + lrow * 128 + cb);
        cp16(krow_s + (cb ^ lswz), Kg + (size_t)(kb0 + lrow) * 128 + cb);
        cp16(vrow_s + (cb ^ lswz), Vg + (size_t)(kb0 + lrow) * 128 + cb);
    }
    cp_commit();

    const int grp = lane >> 3;
    const int li = lane & 7;
    const int g = lane >> 2;
    const int tg = lane & 3;
    const int row0 = w * 16 + g;
    const int qg0 = q0 + row0;
    const int qg1 = qg0 + 8;

    cp_wait<0>();
    __syncthreads();

    uint32_t aQ[4][4];
    {
        const int qr = w * 16 + li + (grp & 1) * 8;
        const uint32_t qa = Qs + qr * 128;
        const int qsw = (qr & 7) << 4;
        const int qg16 = (grp >> 1) * 16;
#pragma unroll
        for (int kk = 0; kk < 4; kk++)
            ldsm4(aQ[kk], qa + ((kk * 32 + qg16) ^ qsw));
    }

    const int lo0 = lo_s[row0];
    const int lo1 = lo_s[row0 + 8];

    uint32_t k_ro[4]; int k_sw[4];
    uint32_t v_co[4];
#pragma unroll
    for (int nb = 0; nb < 4; nb++) {
        const int r = nb * 16 + li + (grp >> 1) * 8;
        k_ro[nb] = r * 128;
        k_sw[nb] = (r & 7) << 4;
        v_co[nb] = nb * 32 + (grp >> 1) * 16;
    }
    const int k_g16 = (grp & 1) * 16;
    const int v_r8 = (grp & 1) * 8 + li;

    float m0 = -1e30f, m1 = -1e30f, l0 = 0.f, l1 = 0.f;
    float o[8][4];
#pragma unroll
    for (int jn = 0; jn < 8; jn++)
#pragma unroll
        for (int r = 0; r < 4; r++) o[jn][r] = 0.f;

    for (int i = 0; i < nt; i++) {
        const int kb = kb0 + i * 64;
        if (i + 1 < nt) {
            const int bo = ((i + 1) & 1) * 8192;
            const size_t go = (size_t)(kb + 64 + lrow) * 128;
#pragma unroll
            for (int c2 = 0; c2 < 4; c2++) {
                const int cb = lcb0 + c2 * 16;
                cp16(krow_s + bo + (cb ^ lswz), Kg + go + cb);
                cp16(vrow_s + bo + (cb ^ lswz), Vg + go + cb);
            }
        }
        cp_commit();
        cp_wait<1>();
        __syncthreads();

        const uint32_t Kb = Ks + (i & 1) * 8192;
        const uint32_t Vb = Vs + (i & 1) * 8192;

        float sc[8][4];
#pragma unroll
        for (int j = 0; j < 8; j++)
#pragma unroll
            for (int r = 0; r < 4; r++) sc[j][r] = 0.f;

#pragma unroll
        for (int kk = 0; kk < 4; kk++) {
            uint32_t bfr[4][4];
#pragma unroll
            for (int nb = 0; nb < 4; nb++)
                ldsm4(bfr[nb], Kb + k_ro[nb] + ((kk * 32 + k_g16) ^ k_sw[nb]));
#pragma unroll
            for (int j = 0; j < 8; j++)
                mma_f16(sc[j], aQ[kk], &bfr[j >> 1][(j & 1) * 2]);
        }

        float mx0 = -1e30f, mx1 = -1e30f;
#pragma unroll
        for (int j = 0; j < 8; j++) {
            const int c0 = kb + j * 8 + tg * 2;
            const int c1 = c0 + 1;
            if (c0 < lo0 || c0 > qg0) sc[j][0] = -1e30f;
            if (c1 < lo0 || c1 > qg0) sc[j][1] = -1e30f;
            if (c0 < lo1 || c0 > qg1) sc[j][2] = -1e30f;
            if (c1 < lo1 || c1 > qg1) sc[j][3] = -1e30f;
            mx0 = fmaxf(mx0, fmaxf(sc[j][0], sc[j][1]));
            mx1 = fmaxf(mx1, fmaxf(sc[j][2], sc[j][3]));
        }
        mx0 = fmaxf(mx0, __shfl_xor_sync(0xffffffffu, mx0, 1));
        mx0 = fmaxf(mx0, __shfl_xor_sync(0xffffffffu, mx0, 2));
        mx1 = fmaxf(mx1, __shfl_xor_sync(0xffffffffu, mx1, 1));
        mx1 = fmaxf(mx1, __shfl_xor_sync(0xffffffffu, mx1, 2));

        const float mn0 = fmaxf(m0, mx0);
        const float mn1 = fmaxf(m1, mx1);
        const float al0 = __expf(m0 - mn0);
        const float al1 = __expf(m1 - mn1);

        float lp0 = 0.f, lp1 = 0.f;
        uint32_t ph[8][2];
#pragma unroll
        for (int j = 0; j < 8; j++) {
            const float p0 = (sc[j][0] > -1e29f) ? __expf(sc[j][0] - mn0) : 0.f;
            const float p1 = (sc[j][1] > -1e29f) ? __expf(sc[j][1] - mn0) : 0.f;
            const float p2 = (sc[j][2] > -1e29f) ? __expf(sc[j][2] - mn1) : 0.f;
            const float p3 = (sc[j][3] > -1e29f) ? __expf(sc[j][3] - mn1) : 0.f;
            lp0 += p0 + p1;
            lp1 += p2 + p3;
            __half2 h0 = __floats2half2_rn(p0, p1);
            __half2 h1 = __floats2half2_rn(p2, p3);
            ph[j][0] = *(uint32_t*)&h0;
            ph[j][1] = *(uint32_t*)&h1;
        }
        lp0 += __shfl_xor_sync(0xffffffffu, lp0, 1);
        lp0 += __shfl_xor_sync(0xffffffffu, lp0, 2);
        lp1 += __shfl_xor_sync(0xffffffffu, lp1, 1);
        lp1 += __shfl_xor_sync(0xffffffffu, lp1, 2);

        l0 = l0 * al0 + lp0;
        l1 = l1 * al1 + lp1;
        m0 = mn0; m1 = mn1;
#pragma unroll
        for (int jn = 0; jn < 8; jn++) {
            o[jn][0] *= al0; o[jn][1] *= al0;
            o[jn][2] *= al1; o[jn][3] *= al1;
        }

#pragma unroll
        for (int kk = 0; kk < 4; kk++) {
            uint32_t vf[4][4];
            const int vr = kk * 16 + v_r8;
            const uint32_t va = Vb + vr * 128;
            const int vsw = (vr & 7) << 4;
#pragma unroll
            for (int nb = 0; nb < 4; nb++)
                ldsm4t(vf[nb], va + (v_co[nb] ^ vsw));
            uint32_t aP[4] = { ph[2 * kk][0], ph[2 * kk][1],
                               ph[2 * kk + 1][0], ph[2 * kk + 1][1] };
#pragma unroll
            for (int jn = 0; jn < 8; jn++)
                mma_f16(o[jn], aP, &vf[jn >> 1][(jn & 1) * 2]);
        }
        __syncthreads();
    }

    const float iv0 = 1.0f / l0;
    const float iv1 = 1.0f / l1;
    __half* y0 = g_yh + ((size_t)(b * LL) + qg0) * DD + h * HD;
    __half* y1 = g_yh + ((size_t)(b * LL) + qg1) * DD + h * HD;
#pragma unroll
    for (int jn = 0; jn < 8; jn++) {
        __half2 r0 = __floats2half2_rn(o[jn][0] * iv0, o[jn][1] * iv0);
        __half2 r1 = __floats2half2_rn(o[jn][2] * iv1, o[jn][3] * iv1);
        *(__half2*)(y0 + jn * 8 + tg * 2) = r0;
        *(__half2*)(y1 + jn * 8 + tg * 2) = r1;
    }
}

// ---------------- launch ----------------
extern "C" void kernel_launch(void* const* d_in, const int* in_sizes, int n_in,
                              void* d_out, int out_size) {
    const float* x     = (const float*)d_in[0];
    const float* w_qkv = (const float*)d_in[1];
    const float* w_out = (const float*)d_in[2];
    const void*  mask  = d_in[3];
    float* out = (float*)d_out;

    __half *phh, *pwqh, *pwoh, *pyh;
    cudaGetSymbolAddress((void**)&phh, g_hh);
    cudaGetSymbolAddress((void**)&pwqh, g_wqkvh);
    cudaGetSymbolAddress((void**)&pwoh, g_wouth);
    cudaGetSymbolAddress((void**)&pyh, g_yh);

    const int M = BB * LL;

    cudaFuncSetAttribute(hgemm_kernel<1>,
                         cudaFuncAttributeMaxDynamicSharedMemorySize, GSMEM);
    cudaFuncSetAttribute(hgemm_kernel<2>,
                         cudaFuncAttributeMaxDynamicSharedMemorySize, GSMEM);
    cudaFuncSetAttribute(attn_mma_kernel,
                         cudaFuncAttributeMaxDynamicSharedMemorySize, ATT_SMEM);

    prep_kernel<<<NB_TOT, 256>>>(x, w_qkv, w_out, mask);

    hgemm_kernel<2><<<dim3(QKV_DIM / 128, M / 128), 512, GSMEM>>>(
        phh, pwqh, nullptr, nullptr, M, QKV_DIM, DD);

    attn_mma_kernel<<<dim3(LL / 64, NH, BB), 128, ATT_SMEM>>>();

    hgemm_kernel<1><<<dim3(DD / 128, M / 128), 512, GSMEM>>>(
        pyh, pwoh, x, out, M, DD, DD);
}

// round 13
// speedup vs baseline: 1.0868x; 1.0467x over previous
#include <cuda_runtime.h>
#include <cuda_fp16.h>
#include <math.h>
#include <stdint.h>

#define BB 2
#define LL 2048
#define DD 1024
#define NH 16
#define NKV 4
#define HD 64
#define WIN 1024
#define QKV_DIM 1536
#define EPSV 1.1920929e-07f

// ---------------- scratch (no cudaMalloc allowed) ----------------
__device__ __half g_hh[BB * LL * DD];
__device__ __half g_wqkvh[QKV_DIM * DD];
__device__ __half g_wouth[DD * DD];
__device__ __half g_yh[BB * LL * DD];
__device__ __half g_qh[BB * NH * LL * HD];
__device__ __half g_kh[BB * NKV * LL * HD];
__device__ __half g_vh[BB * NKV * LL * HD];
__device__ int    g_lo[BB * LL];
__device__ float4 g_rope[LL * 16];

// ---------------- ptx helpers ----------------
__device__ __forceinline__ uint32_t smem_u32(const void* p) {
    uint32_t a;
    asm("{ .reg .u64 t; cvta.to.shared.u64 t, %1; cvt.u32.u64 %0, t; }"
        : "=r"(a) : "l"(p));
    return a;
}
__device__ __forceinline__ void cp16(uint32_t smem_dst, const void* gsrc) {
    asm volatile("cp.async.cg.shared.global [%0], [%1], 16;\n"
                 :: "r"(smem_dst), "l"(gsrc));
}
__device__ __forceinline__ void cp_commit() {
    asm volatile("cp.async.commit_group;\n");
}
template <int N>
__device__ __forceinline__ void cp_wait() {
    asm volatile("cp.async.wait_group %0;\n" :: "n"(N));
}
__device__ __forceinline__ void ldsm4(uint32_t* r, uint32_t addr) {
    asm volatile("ldmatrix.sync.aligned.m8n8.x4.shared.b16 {%0,%1,%2,%3}, [%4];"
                 : "=r"(r[0]), "=r"(r[1]), "=r"(r[2]), "=r"(r[3]) : "r"(addr));
}
__device__ __forceinline__ void ldsm4t(uint32_t* r, uint32_t addr) {
    asm volatile("ldmatrix.sync.aligned.m8n8.x4.trans.shared.b16 {%0,%1,%2,%3}, [%4];"
                 : "=r"(r[0]), "=r"(r[1]), "=r"(r[2]), "=r"(r[3]) : "r"(addr));
}
__device__ __forceinline__ void mma_f16(float* c, const uint32_t* a, const uint32_t* b) {
    asm volatile(
        "mma.sync.aligned.m16n8k16.row.col.f32.f16.f16.f32 "
        "{%0,%1,%2,%3}, {%4,%5,%6,%7}, {%8,%9}, {%0,%1,%2,%3};"
        : "+f"(c[0]), "+f"(c[1]), "+f"(c[2]), "+f"(c[3])
        : "r"(a[0]), "r"(a[1]), "r"(a[2]), "r"(a[3]), "r"(b[0]), "r"(b[1]));
}

// ---------------- fused prep kernel ----------------
#define NB_SEG  BB
#define NB_ROPE 128
#define NB_CONV 2560
#define NB_RMS  (BB * LL)
#define NB_TOT  (NB_SEG + NB_ROPE + NB_CONV + NB_RMS)

__global__ void __launch_bounds__(256) prep_kernel(
    const float* __restrict__ x, const float* __restrict__ wq,
    const float* __restrict__ wo, const void* __restrict__ mask)
{
    const int bid = blockIdx.x;
    const int t = threadIdx.x;

    if (bid < NB_SEG) {
        __shared__ int sA[256];
        __shared__ int sB[256];
        __shared__ int encs;
        const int b = bid;
        if (t == 0) {
            const unsigned* mi = (const unsigned*)mask;
            int e = 0;
            for (int i = 0; i < 64; i++) {
                unsigned v = mi[i];
                if (v == 0x3F800000u) { e = 2; break; }
                if (v > 1u) e = 1;
            }
            encs = e;
        }
        __syncthreads();
        const int e = encs;

        int pref[8];
        int run = 0;
        const int base = t * 8;
#pragma unroll
        for (int i = 0; i < 8; i++) {
            const int idx = base + i;
            int mset;
            if (e == 0)      mset = ((const int*)mask)[b * LL + idx] != 0;
            else if (e == 1) mset = ((const unsigned char*)mask)[b * LL + idx] != 0;
            else             mset = ((const float*)mask)[b * LL + idx] != 0.0f;
            run = max(run, mset ? idx : 0);
            pref[i] = run;
        }
        sA[t] = run;
        __syncthreads();
        int* s = sA;
        int* d = sB;
        for (int off = 1; off < 256; off <<= 1) {
            int v = s[t];
            if (t >= off) v = max(v, s[t - off]);
            d[t] = v;
            __syncthreads();
            int* tmp = s; s = d; d = tmp;
        }
        const int excl = (t > 0) ? s[t - 1] : 0;
#pragma unroll
        for (int i = 0; i < 8; i++) {
            const int idx = base + i;
            g_lo[b * LL + idx] = max(idx - (WIN - 1), max(excl, pref[i]));
        }
    } else if (bid < NB_SEG + NB_ROPE) {
        const int i = (bid - NB_SEG) * 256 + t;
        const int l = i >> 4;
        const int j = (i & 15) * 2;
        const float lg = logf(10000.0f) * (1.0f / 32.0f);
        const float f0 = expf(-lg * (float)j);
        const float f1 = expf(-lg * (float)(j + 1));
        float s0, c0, s1, c1;
        sincosf((float)l * f0, &s0, &c0);
        sincosf((float)l * f1, &s1, &c1);
        g_rope[i] = make_float4(c0, c1, s0, s1);
    } else if (bid < NB_SEG + NB_ROPE + NB_CONV) {
        const int n1 = QKV_DIM * DD;
        const int i = ((bid - NB_SEG - NB_ROPE) * 256 + t) * 4;
        if (i < n1) {
            float4 v = *(const float4*)(wq + i);
            *(__half2*)(g_wqkvh + i) = __floats2half2_rn(v.x, v.y);
            *(__half2*)(g_wqkvh + i + 2) = __floats2half2_rn(v.z, v.w);
        } else {
            const int k = i - n1;
            float4 v = *(const float4*)(wo + k);
            *(__half2*)(g_wouth + k) = __floats2half2_rn(v.x, v.y);
            *(__half2*)(g_wouth + k + 2) = __floats2half2_rn(v.z, v.w);
        }
    } else {
        const int row = bid - (NB_SEG + NB_ROPE + NB_CONV);
        const float4* xr = (const float4*)(x + (size_t)row * DD);
        __half2* hr = (__half2*)(g_hh + (size_t)row * DD);
        const float4 v = xr[t];
        float ss = v.x * v.x + v.y * v.y + v.z * v.z + v.w * v.w;

        __shared__ float red[8];
#pragma unroll
        for (int m = 16; m; m >>= 1) ss += __shfl_xor_sync(0xffffffffu, ss, m);
        if ((t & 31) == 0) red[t >> 5] = ss;
        __syncthreads();
        if (t < 8) {
            float r = red[t];
#pragma unroll
            for (int m = 4; m; m >>= 1) r += __shfl_xor_sync(0xffu, r, m, 8);
            if (t == 0) red[0] = r;
        }
        __syncthreads();
        const float inv = rsqrtf(red[0] * (1.0f / DD) + EPSV);
        hr[t * 2] = __floats2half2_rn(v.x * inv, v.y * inv);
        hr[t * 2 + 1] = __floats2half2_rn(v.z * inv, v.w * inv);
    }
}

// ---------------- fp16 mma.sync GEMM: 128x64 tile, 8 warps, 2 CTAs/SM ----------------
// BK=64, NSTG=3. A stage 16KB, B stage 8KB -> 72KB/CTA -> 2 CTAs/SM.
// Warp tile 32x32 (4m x 2n). Round-10's verified fragment path, barrier at ks==3.
// EPI=1: C = A@W^T + res. EPI=2: fused per-head rmsnorm+rope (one head per tile).
#define NSTG 3
#define STG_A (128 * 128)   // 16KB
#define STG_BB (64 * 128)   // 8KB
#define GSMEM (NSTG * (STG_A + STG_BB))   // 73728

template <int EPI>
__global__ void __launch_bounds__(256, 2) hgemm_kernel(
    const __half* __restrict__ A, const __half* __restrict__ W,
    const float* __restrict__ res, float* __restrict__ C,
    int M, int N, int K)
{
    extern __shared__ char smem[];
    const uint32_t sb = smem_u32(smem);
    const uint32_t Asm = sb;
    const uint32_t Bsm = sb + NSTG * STG_A;

    const int t = threadIdx.x;
    const int lane = t & 31;
    const int wid = t >> 5;               // 0..7
    const int wm = (wid & 3) * 32;        // 4 m-warps
    const int wn = (wid >> 2) * 32;       // 2 n-warps
    const int m0 = blockIdx.y * 128;
    const int n0 = blockIdx.x * 64;

    // loaders: A row t/2, 4x16B at (t&1)*64+i*16; B row t/4, 2x16B at (t&3)*32
    const int lrA = t >> 1;
    const int lcA = (t & 1) * 64;
    const int lswA = (lrA & 7) << 4;
    const int lrB = t >> 2;
    const int lcB = (t & 3) * 32;
    const int lswB = (lrB & 7) << 4;
    const char* Agb = (const char*)(A + (size_t)(m0 + lrA) * K);
    const char* Wgb = (const char*)(W + (size_t)(n0 + lrB) * K);
    const uint32_t arow = Asm + lrA * 128;
    const uint32_t brow = Bsm + lrB * 128;

    float acc[2][4][4];
#pragma unroll
    for (int i = 0; i < 2; i++)
#pragma unroll
        for (int j = 0; j < 4; j++)
#pragma unroll
            for (int r = 0; r < 4; r++) acc[i][j][r] = 0.f;

    const int grp = lane >> 3;
    const int li = lane & 7;
    uint32_t a_ro[2]; int a_sw[2];
    uint32_t b_ro[2]; int b_sw[2];
#pragma unroll
    for (int mi = 0; mi < 2; mi++) {
        const int r = wm + mi * 16 + li + (grp & 1) * 8;
        a_ro[mi] = r * 128;
        a_sw[mi] = (r & 7) << 4;
    }
#pragma unroll
    for (int nb = 0; nb < 2; nb++) {
        const int r = wn + nb * 16 + li + (grp >> 1) * 8;
        b_ro[nb] = r * 128;
        b_sw[nb] = (r & 7) << 4;
    }
    const int a_g16 = (grp >> 1) * 16;
    const int b_g16 = (grp & 1) * 16;

    const int nch = K >> 6;

    // preload stages 0..NSTG-2
#pragma unroll
    for (int s = 0; s < NSTG - 1; s++) {
#pragma unroll
        for (int i = 0; i < 4; i++) {
            const int cb = lcA + i * 16;
            cp16(arow + s * STG_A + (cb ^ lswA), Agb + s * 128 + cb);
        }
#pragma unroll
        for (int i = 0; i < 2; i++) {
            const int cb = lcB + i * 16;
            cp16(brow + s * STG_BB + (cb ^ lswB), Wgb + s * 128 + cb);
        }
        cp_commit();
    }

    cp_wait<NSTG - 2>();
    __syncthreads();

    // fragment double buffers
    uint32_t af[2][2][4], bf[2][2][4];
#pragma unroll
    for (int mi = 0; mi < 2; mi++)
        ldsm4(af[0][mi], Asm + a_ro[mi] + (a_g16 ^ a_sw[mi]));
#pragma unroll
    for (int nb = 0; nb < 2; nb++)
        ldsm4(bf[0][nb], Bsm + b_ro[nb] + (b_g16 ^ b_sw[nb]));

    int buf = 0;
    for (int c = 0; c < nch; c++) {
        const uint32_t as = Asm + (c % NSTG) * STG_A;
        const uint32_t bs = Bsm + (c % NSTG) * STG_BB;
        const uint32_t asn = Asm + ((c + 1) % NSTG) * STG_A;
        const uint32_t bsn = Bsm + ((c + 1) % NSTG) * STG_BB;

#pragma unroll
        for (int ks = 0; ks < 4; ks++) {
            if (ks == 3) {
                cp_wait<NSTG - 2>();
                __syncthreads();
            }
            if (c < nch - 1 || ks < 3) {
                const uint32_t las = (ks < 3) ? as : asn;
                const uint32_t lbs = (ks < 3) ? bs : bsn;
                const int koff = ((ks + 1) & 3) * 32;
#pragma unroll
                for (int mi = 0; mi < 2; mi++)
                    ldsm4(af[buf ^ 1][mi], las + a_ro[mi] + ((koff + a_g16) ^ a_sw[mi]));
#pragma unroll
                for (int nb = 0; nb < 2; nb++)
                    ldsm4(bf[buf ^ 1][nb], lbs + b_ro[nb] + ((koff + b_g16) ^ b_sw[nb]));
            }
            if (ks == 0) {
                const int pf = c + NSTG - 1;
                if (pf < nch) {
                    const int sA2 = (pf % NSTG) * STG_A;
                    const int sB2 = (pf % NSTG) * STG_BB;
#pragma unroll
                    for (int i = 0; i < 4; i++) {
                        const int cb = lcA + i * 16;
                        cp16(arow + sA2 + (cb ^ lswA), Agb + (size_t)pf * 128 + cb);
                    }
#pragma unroll
                    for (int i = 0; i < 2; i++) {
                        const int cb = lcB + i * 16;
                        cp16(brow + sB2 + (cb ^ lswB), Wgb + (size_t)pf * 128 + cb);
                    }
                }
                cp_commit();
            }
#pragma unroll
            for (int mi = 0; mi < 2; mi++)
#pragma unroll
                for (int ni = 0; ni < 4; ni++)
                    mma_f16(acc[mi][ni], af[buf][mi], &bf[buf][ni >> 1][(ni & 1) * 2]);
            buf ^= 1;
        }
    }

    const int g = lane >> 2;
    const int tg = lane & 3;

    if (EPI == 1) {
#pragma unroll
        for (int mi = 0; mi < 2; mi++) {
#pragma unroll
            for (int ni = 0; ni < 4; ni++) {
                const int row = m0 + wm + mi * 16 + g;
                const int col = n0 + wn + ni * 8 + tg * 2;
                float2 v0 = make_float2(acc[mi][ni][0], acc[mi][ni][1]);
                float2 v1 = make_float2(acc[mi][ni][2], acc[mi][ni][3]);
                const float2 r0 = *(const float2*)(res + (size_t)row * N + col);
                const float2 r1 = *(const float2*)(res + (size_t)(row + 8) * N + col);
                v0.x += r0.x; v0.y += r0.y;
                v1.x += r1.x; v1.y += r1.y;
                *(float2*)(C + (size_t)row * N + col) = v0;
                *(float2*)(C + (size_t)(row + 8) * N + col) = v1;
            }
        }
    } else {
        // ---- fused qkv epilogue: one head per tile (64 cols) ----
        __syncthreads();
        float* sf = (float*)smem;  // [128][68] = 34816 B
#pragma unroll
        for (int mi = 0; mi < 2; mi++) {
#pragma unroll
            for (int ni = 0; ni < 4; ni++) {
                const int r = wm + mi * 16 + g;
                const int cl = wn + ni * 8 + tg * 2;
                *(float2*)&sf[r * 68 + cl] = make_float2(acc[mi][ni][0], acc[mi][ni][1]);
                *(float2*)&sf[(r + 8) * 68 + cl] = make_float2(acc[mi][ni][2], acc[mi][ni][3]);
            }
        }
        __syncthreads();

        const int gi = t >> 4;        // 0..15
        const int tl = t & 15;
        const int j = tl * 2;
        const int head = n0 >> 6;

        for (int it = 0; it < 8; it++) {
            const int r = it * 16 + gi;   // 128 rows
            const int rowg = m0 + r;
            const int b = rowg >> 11;
            const int l = rowg & (LL - 1);
            const float* sr = &sf[r * 68];

            const float a0 = sr[j], a1 = sr[j + 1];
            const float b0 = sr[j + 32], b1 = sr[j + 33];

            if (head < 20) {
                float ss = a0 * a0 + a1 * a1 + b0 * b0 + b1 * b1;
#pragma unroll
                for (int m = 8; m; m >>= 1)
                    ss += __shfl_xor_sync(0xffffffffu, ss, m, 16);
                const float inv = rsqrtf(ss * (1.0f / HD) + EPSV);
                const float4 rp = g_rope[l * 16 + tl];
                const float a0n = a0 * inv, a1n = a1 * inv;
                const float b0n = b0 * inv, b1n = b1 * inv;
                const float o0 = a0n * rp.x - b0n * rp.z;
                const float o1 = a1n * rp.y - b1n * rp.w;
                const float o2 = a0n * rp.z + b0n * rp.x;
                const float o3 = a1n * rp.w + b1n * rp.y;
                if (head < 16) {
                    const float sc = 0.125f;
                    __half* dq = g_qh + (((size_t)(b * NH + head)) * LL + l) * HD;
                    *(__half2*)(dq + j) = __floats2half2_rn(o0 * sc, o1 * sc);
                    *(__half2*)(dq + j + 32) = __floats2half2_rn(o2 * sc, o3 * sc);
                } else {
                    __half* dk = g_kh + (((size_t)(b * NKV + (head - 16))) * LL + l) * HD;
                    *(__half2*)(dk + j) = __floats2half2_rn(o0, o1);
                    *(__half2*)(dk + j + 32) = __floats2half2_rn(o2, o3);
                }
            } else {
                __half* dv = g_vh + (((size_t)(b * NKV + (head - 20))) * LL + l) * HD;
                *(__half2*)(dv + j) = __floats2half2_rn(a0, a1);
                *(__half2*)(dv + j + 32) = __floats2half2_rn(b0, b1);
            }
        }
    }
}

// ---------------- tensor-core flash attention ----------------
#define ATT_SMEM (5 * 8192)
__global__ void __launch_bounds__(128) attn_mma_kernel() {
    extern __shared__ char smc[];
    const uint32_t sb = smem_u32(smc);
    const uint32_t Qs = sb;
    const uint32_t Ks = sb + 8192;
    const uint32_t Vs = sb + 3 * 8192;
    __shared__ int lo_s[64];

    const int qb = blockIdx.x, h = blockIdx.y, b = blockIdx.z;
    const int t = threadIdx.x;
    const int lane = t & 31;
    const int w = t >> 5;
    const int q0 = qb * 64;
    const int kvh = h >> 2;
    const char* Qg = (const char*)(g_qh + (((size_t)(b * NH + h)) * LL + q0) * HD);
    const char* Kg = (const char*)(g_kh + ((size_t)(b * NKV + kvh)) * LL * HD);
    const char* Vg = (const char*)(g_vh + ((size_t)(b * NKV + kvh)) * LL * HD);

    const int kb0 = g_lo[b * LL + q0] & ~63;
    const int nt = ((q0 + 63 - kb0) >> 6) + 1;
    if (t < 64) lo_s[t] = g_lo[b * LL + q0 + t];

    const int lrow = t >> 1;
    const int lcb0 = (t & 1) * 64;
    const int lswz = (lrow & 7) << 4;
    const uint32_t qrow_s = Qs + lrow * 128;
    const uint32_t krow_s = Ks + lrow * 128;
    const uint32_t vrow_s = Vs + lrow * 128;

#pragma unroll
    for (int i = 0; i < 4; i++) {
        const int cb = lcb0 + i * 16;
        cp16(qrow_s + (cb ^ lswz), Qg + lrow * 128 + cb);
        cp16(krow_s + (cb ^ lswz), Kg + (size_t)(kb0 + lrow) * 128 + cb);
        cp16(vrow_s + (cb ^ lswz), Vg + (size_t)(kb0 + lrow) * 128 + cb);
    }
    cp_commit();

    const int grp = lane >> 3;
    const int li = lane & 7;
    const int g = lane >> 2;
    const int tg = lane & 3;
    const int row0 = w * 16 + g;
    const int qg0 = q0 + row0;
    const int qg1 = qg0 + 8;

    cp_wait<0>();
    __syncthreads();

    uint32_t aQ[4][4];
    {
        const int qr = w * 16 + li + (grp & 1) * 8;
        const uint32_t qa = Qs + qr * 128;
        const int qsw = (qr & 7) << 4;
        const int qg16 = (grp >> 1) * 16;
#pragma unroll
        for (int kk = 0; kk < 4; kk++)
            ldsm4(aQ[kk], qa + ((kk * 32 + qg16) ^ qsw));
    }

    const int lo0 = lo_s[row0];
    const int lo1 = lo_s[row0 + 8];

    uint32_t k_ro[4]; int k_sw[4];
    uint32_t v_co[4];
#pragma unroll
    for (int nb = 0; nb < 4; nb++) {
        const int r = nb * 16 + li + (grp >> 1) * 8;
        k_ro[nb] = r * 128;
        k_sw[nb] = (r & 7) << 4;
        v_co[nb] = nb * 32 + (grp >> 1) * 16;
    }
    const int k_g16 = (grp & 1) * 16;
    const int v_r8 = (grp & 1) * 8 + li;

    float m0 = -1e30f, m1 = -1e30f, l0 = 0.f, l1 = 0.f;
    float o[8][4];
#pragma unroll
    for (int jn = 0; jn < 8; jn++)
#pragma unroll
        for (int r = 0; r < 4; r++) o[jn][r] = 0.f;

    for (int i = 0; i < nt; i++) {
        const int kb = kb0 + i * 64;
        if (i + 1 < nt) {
            const int bo = ((i + 1) & 1) * 8192;
            const size_t go = (size_t)(kb + 64 + lrow) * 128;
#pragma unroll
            for (int c2 = 0; c2 < 4; c2++) {
                const int cb = lcb0 + c2 * 16;
                cp16(krow_s + bo + (cb ^ lswz), Kg + go + cb);
                cp16(vrow_s + bo + (cb ^ lswz), Vg + go + cb);
            }
        }
        cp_commit();
        cp_wait<1>();
        __syncthreads();

        const uint32_t Kb = Ks + (i & 1) * 8192;
        const uint32_t Vb = Vs + (i & 1) * 8192;

        float sc[8][4];
#pragma unroll
        for (int j = 0; j < 8; j++)
#pragma unroll
            for (int r = 0; r < 4; r++) sc[j][r] = 0.f;

#pragma unroll
        for (int kk = 0; kk < 4; kk++) {
            uint32_t bfr[4][4];
#pragma unroll
            for (int nb = 0; nb < 4; nb++)
                ldsm4(bfr[nb], Kb + k_ro[nb] + ((kk * 32 + k_g16) ^ k_sw[nb]));
#pragma unroll
            for (int j = 0; j < 8; j++)
                mma_f16(sc[j], aQ[kk], &bfr[j >> 1][(j & 1) * 2]);
        }

        float mx0 = -1e30f, mx1 = -1e30f;
#pragma unroll
        for (int j = 0; j < 8; j++) {
            const int c0 = kb + j * 8 + tg * 2;
            const int c1 = c0 + 1;
            if (c0 < lo0 || c0 > qg0) sc[j][0] = -1e30f;
            if (c1 < lo0 || c1 > qg0) sc[j][1] = -1e30f;
            if (c0 < lo1 || c0 > qg1) sc[j][2] = -1e30f;
            if (c1 < lo1 || c1 > qg1) sc[j][3] = -1e30f;
            mx0 = fmaxf(mx0, fmaxf(sc[j][0], sc[j][1]));
            mx1 = fmaxf(mx1, fmaxf(sc[j][2], sc[j][3]));
        }
        mx0 = fmaxf(mx0, __shfl_xor_sync(0xffffffffu, mx0, 1));
        mx0 = fmaxf(mx0, __shfl_xor_sync(0xffffffffu, mx0, 2));
        mx1 = fmaxf(mx1, __shfl_xor_sync(0xffffffffu, mx1, 1));
        mx1 = fmaxf(mx1, __shfl_xor_sync(0xffffffffu, mx1, 2));

        const float mn0 = fmaxf(m0, mx0);
        const float mn1 = fmaxf(m1, mx1);
        const float al0 = __expf(m0 - mn0);
        const float al1 = __expf(m1 - mn1);

        float lp0 = 0.f, lp1 = 0.f;
        uint32_t ph[8][2];
#pragma unroll
        for (int j = 0; j < 8; j++) {
            const float p0 = (sc[j][0] > -1e29f) ? __expf(sc[j][0] - mn0) : 0.f;
            const float p1 = (sc[j][1] > -1e29f) ? __expf(sc[j][1] - mn0) : 0.f;
            const float p2 = (sc[j][2] > -1e29f) ? __expf(sc[j][2] - mn1) : 0.f;
            const float p3 = (sc[j][3] > -1e29f) ? __expf(sc[j][3] - mn1) : 0.f;
            lp0 += p0 + p1;
            lp1 += p2 + p3;
            __half2 h0 = __floats2half2_rn(p0, p1);
            __half2 h1 = __floats2half2_rn(p2, p3);
            ph[j][0] = *(uint32_t*)&h0;
            ph[j][1] = *(uint32_t*)&h1;
        }
        lp0 += __shfl_xor_sync(0xffffffffu, lp0, 1);
        lp0 += __shfl_xor_sync(0xffffffffu, lp0, 2);
        lp1 += __shfl_xor_sync(0xffffffffu, lp1, 1);
        lp1 += __shfl_xor_sync(0xffffffffu, lp1, 2);

        l0 = l0 * al0 + lp0;
        l1 = l1 * al1 + lp1;
        m0 = mn0; m1 = mn1;
#pragma unroll
        for (int jn = 0; jn < 8; jn++) {
            o[jn][0] *= al0; o[jn][1] *= al0;
            o[jn][2] *= al1; o[jn][3] *= al1;
        }

#pragma unroll
        for (int kk = 0; kk < 4; kk++) {
            uint32_t vf[4][4];
            const int vr = kk * 16 + v_r8;
            const uint32_t va = Vb + vr * 128;
            const int vsw = (vr & 7) << 4;
#pragma unroll
            for (int nb = 0; nb < 4; nb++)
                ldsm4t(vf[nb], va + (v_co[nb] ^ vsw));
            uint32_t aP[4] = { ph[2 * kk][0], ph[2 * kk][1],
                               ph[2 * kk + 1][0], ph[2 * kk + 1][1] };
#pragma unroll
            for (int jn = 0; jn < 8; jn++)
                mma_f16(o[jn], aP, &vf[jn >> 1][(jn & 1) * 2]);
        }
        __syncthreads();
    }

    const float iv0 = 1.0f / l0;
    const float iv1 = 1.0f / l1;
    __half* y0 = g_yh + ((size_t)(b * LL) + qg0) * DD + h * HD;
    __half* y1 = g_yh + ((size_t)(b * LL) + qg1) * DD + h * HD;
#pragma unroll
    for (int jn = 0; jn < 8; jn++) {
        __half2 r0 = __floats2half2_rn(o[jn][0] * iv0, o[jn][1] * iv0);
        __half2 r1 = __floats2half2_rn(o[jn][2] * iv1, o[jn][3] * iv1);
        *(__half2*)(y0 + jn * 8 + tg * 2) = r0;
        *(__half2*)(y1 + jn * 8 + tg * 2) = r1;
    }
}

// ---------------- launch ----------------
extern "C" void kernel_launch(void* const* d_in, const int* in_sizes, int n_in,
                              void* d_out, int out_size) {
    const float* x     = (const float*)d_in[0];
    const float* w_qkv = (const float*)d_in[1];
    const float* w_out = (const float*)d_in[2];
    const void*  mask  = d_in[3];
    float* out = (float*)d_out;

    __half *phh, *pwqh, *pwoh, *pyh;
    cudaGetSymbolAddress((void**)&phh, g_hh);
    cudaGetSymbolAddress((void**)&pwqh, g_wqkvh);
    cudaGetSymbolAddress((void**)&pwoh, g_wouth);
    cudaGetSymbolAddress((void**)&pyh, g_yh);

    const int M = BB * LL;

    cudaFuncSetAttribute(hgemm_kernel<1>,
                         cudaFuncAttributeMaxDynamicSharedMemorySize, GSMEM);
    cudaFuncSetAttribute(hgemm_kernel<2>,
                         cudaFuncAttributeMaxDynamicSharedMemorySize, GSMEM);
    cudaFuncSetAttribute(attn_mma_kernel,
                         cudaFuncAttributeMaxDynamicSharedMemorySize, ATT_SMEM);

    prep_kernel<<<NB_TOT, 256>>>(x, w_qkv, w_out, mask);

    hgemm_kernel<2><<<dim3(QKV_DIM / 64, M / 128), 256, GSMEM>>>(
        phh, pwqh, nullptr, nullptr, M, QKV_DIM, DD);

    attn_mma_kernel<<<dim3(LL / 64, NH, BB), 128, ATT_SMEM>>>();

    hgemm_kernel<1><<<dim3(DD / 64, M / 128), 256, GSMEM>>>(
        pyh, pwoh, x, out, M, DD, DD);
}

// round 14
// speedup vs baseline: 1.1345x; 1.0439x over previous
#include <cuda_runtime.h>
#include <cuda_fp16.h>
#include <math.h>
#include <stdint.h>

#define BB 2
#define LL 2048
#define DD 1024
#define NH 16
#define NKV 4
#define HD 64
#define WIN 1024
#define QKV_DIM 1536
#define EPSV 1.1920929e-07f

// ---------------- scratch (no cudaMalloc allowed) ----------------
__device__ __half g_hh[BB * LL * DD];
__device__ __half g_wqkvh[QKV_DIM * DD];
__device__ __half g_wouth[DD * DD];
__device__ __half g_yh[BB * LL * DD];
__device__ __half g_qh[BB * NH * LL * HD];
__device__ __half g_kh[BB * NKV * LL * HD];
__device__ __half g_vh[BB * NKV * LL * HD];
__device__ int    g_lo[BB * LL];
__device__ float4 g_rope[LL * 16];

// ---------------- ptx helpers ----------------
__device__ __forceinline__ uint32_t smem_u32(const void* p) {
    uint32_t a;
    asm("{ .reg .u64 t; cvta.to.shared.u64 t, %1; cvt.u32.u64 %0, t; }"
        : "=r"(a) : "l"(p));
    return a;
}
__device__ __forceinline__ void cp16(uint32_t smem_dst, const void* gsrc) {
    asm volatile("cp.async.cg.shared.global [%0], [%1], 16;\n"
                 :: "r"(smem_dst), "l"(gsrc));
}
__device__ __forceinline__ void cp_commit() {
    asm volatile("cp.async.commit_group;\n");
}
template <int N>
__device__ __forceinline__ void cp_wait() {
    asm volatile("cp.async.wait_group %0;\n" :: "n"(N));
}
__device__ __forceinline__ void ldsm4(uint32_t* r, uint32_t addr) {
    asm volatile("ldmatrix.sync.aligned.m8n8.x4.shared.b16 {%0,%1,%2,%3}, [%4];"
                 : "=r"(r[0]), "=r"(r[1]), "=r"(r[2]), "=r"(r[3]) : "r"(addr));
}
__device__ __forceinline__ void ldsm4t(uint32_t* r, uint32_t addr) {
    asm volatile("ldmatrix.sync.aligned.m8n8.x4.trans.shared.b16 {%0,%1,%2,%3}, [%4];"
                 : "=r"(r[0]), "=r"(r[1]), "=r"(r[2]), "=r"(r[3]) : "r"(addr));
}
__device__ __forceinline__ void mma_f16(float* c, const uint32_t* a, const uint32_t* b) {
    asm volatile(
        "mma.sync.aligned.m16n8k16.row.col.f32.f16.f16.f32 "
        "{%0,%1,%2,%3}, {%4,%5,%6,%7}, {%8,%9}, {%0,%1,%2,%3};"
        : "+f"(c[0]), "+f"(c[1]), "+f"(c[2]), "+f"(c[3])
        : "r"(a[0]), "r"(a[1]), "r"(a[2]), "r"(a[3]), "r"(b[0]), "r"(b[1]));
}

// ---------------- fused prep kernel ----------------
#define NB_SEG  BB
#define NB_ROPE 128
#define NB_CONV 2560
#define NB_RMS  (BB * LL)
#define NB_TOT  (NB_SEG + NB_ROPE + NB_CONV + NB_RMS)

__global__ void __launch_bounds__(256) prep_kernel(
    const float* __restrict__ x, const float* __restrict__ wq,
    const float* __restrict__ wo, const void* __restrict__ mask)
{
    const int bid = blockIdx.x;
    const int t = threadIdx.x;

    if (bid < NB_SEG) {
        __shared__ int sA[256];
        __shared__ int sB[256];
        __shared__ int encs;
        const int b = bid;
        if (t == 0) {
            const unsigned* mi = (const unsigned*)mask;
            int e = 0;
            for (int i = 0; i < 64; i++) {
                unsigned v = mi[i];
                if (v == 0x3F800000u) { e = 2; break; }
                if (v > 1u) e = 1;
            }
            encs = e;
        }
        __syncthreads();
        const int e = encs;

        int pref[8];
        int run = 0;
        const int base = t * 8;
#pragma unroll
        for (int i = 0; i < 8; i++) {
            const int idx = base + i;
            int mset;
            if (e == 0)      mset = ((const int*)mask)[b * LL + idx] != 0;
            else if (e == 1) mset = ((const unsigned char*)mask)[b * LL + idx] != 0;
            else             mset = ((const float*)mask)[b * LL + idx] != 0.0f;
            run = max(run, mset ? idx : 0);
            pref[i] = run;
        }
        sA[t] = run;
        __syncthreads();
        int* s = sA;
        int* d = sB;
        for (int off = 1; off < 256; off <<= 1) {
            int v = s[t];
            if (t >= off) v = max(v, s[t - off]);
            d[t] = v;
            __syncthreads();
            int* tmp = s; s = d; d = tmp;
        }
        const int excl = (t > 0) ? s[t - 1] : 0;
#pragma unroll
        for (int i = 0; i < 8; i++) {
            const int idx = base + i;
            g_lo[b * LL + idx] = max(idx - (WIN - 1), max(excl, pref[i]));
        }
    } else if (bid < NB_SEG + NB_ROPE) {
        const int i = (bid - NB_SEG) * 256 + t;
        const int l = i >> 4;
        const int j = (i & 15) * 2;
        const float lg = logf(10000.0f) * (1.0f / 32.0f);
        const float f0 = expf(-lg * (float)j);
        const float f1 = expf(-lg * (float)(j + 1));
        float s0, c0, s1, c1;
        sincosf((float)l * f0, &s0, &c0);
        sincosf((float)l * f1, &s1, &c1);
        g_rope[i] = make_float4(c0, c1, s0, s1);
    } else if (bid < NB_SEG + NB_ROPE + NB_CONV) {
        const int n1 = QKV_DIM * DD;
        const int i = ((bid - NB_SEG - NB_ROPE) * 256 + t) * 4;
        if (i < n1) {
            float4 v = *(const float4*)(wq + i);
            *(__half2*)(g_wqkvh + i) = __floats2half2_rn(v.x, v.y);
            *(__half2*)(g_wqkvh + i + 2) = __floats2half2_rn(v.z, v.w);
        } else {
            const int k = i - n1;
            float4 v = *(const float4*)(wo + k);
            *(__half2*)(g_wouth + k) = __floats2half2_rn(v.x, v.y);
            *(__half2*)(g_wouth + k + 2) = __floats2half2_rn(v.z, v.w);
        }
    } else {
        const int row = bid - (NB_SEG + NB_ROPE + NB_CONV);
        const float4* xr = (const float4*)(x + (size_t)row * DD);
        __half2* hr = (__half2*)(g_hh + (size_t)row * DD);
        const float4 v = xr[t];
        float ss = v.x * v.x + v.y * v.y + v.z * v.z + v.w * v.w;

        __shared__ float red[8];
#pragma unroll
        for (int m = 16; m; m >>= 1) ss += __shfl_xor_sync(0xffffffffu, ss, m);
        if ((t & 31) == 0) red[t >> 5] = ss;
        __syncthreads();
        if (t < 8) {
            float r = red[t];
#pragma unroll
            for (int m = 4; m; m >>= 1) r += __shfl_xor_sync(0xffu, r, m, 8);
            if (t == 0) red[0] = r;
        }
        __syncthreads();
        const float inv = rsqrtf(red[0] * (1.0f / DD) + EPSV);
        hr[t * 2] = __floats2half2_rn(v.x * inv, v.y * inv);
        hr[t * 2 + 1] = __floats2half2_rn(v.z * inv, v.w * inv);
    }
}

// ---------------- fp16 mma.sync GEMM: 512 threads, 16 warps (4/SMSP) ----------------
// ROUND-10 VERIFIED CONFIG. 128x128 tile, BK=64, NSTG=4 (128KB smem, 1 CTA/SM).
// Warp tile 32x32 (4m x 4n). Fragment double-buffered.
#define NSTG 4
#define STG_B (128 * 128)
#define GSMEM (2 * NSTG * STG_B)

template <int EPI>
__global__ void __launch_bounds__(512) hgemm_kernel(
    const __half* __restrict__ A, const __half* __restrict__ W,
    const float* __restrict__ res, float* __restrict__ C,
    int M, int N, int K)
{
    extern __shared__ char smem[];
    const uint32_t sb = smem_u32(smem);
    const uint32_t Asm = sb;
    const uint32_t Bsm = sb + NSTG * STG_B;

    const int t = threadIdx.x;
    const int lane = t & 31;
    const int wid = t >> 5;               // 0..15
    const int wm = (wid & 3) * 32;        // 4 m-warps
    const int wn = (wid >> 2) * 32;       // 4 n-warps
    const int m0 = blockIdx.y * 128;
    const int n0 = blockIdx.x * 128;

    const int lrow = t >> 2;
    const int lcb0 = (t & 3) * 32;
    const int lswz = (lrow & 7) << 4;
    const char* Agb = (const char*)(A + (size_t)(m0 + lrow) * K);
    const char* Wgb = (const char*)(W + (size_t)(n0 + lrow) * K);
    const uint32_t arow = Asm + lrow * 128;
    const uint32_t brow = Bsm + lrow * 128;

    float acc[2][4][4];
#pragma unroll
    for (int i = 0; i < 2; i++)
#pragma unroll
        for (int j = 0; j < 4; j++)
#pragma unroll
            for (int r = 0; r < 4; r++) acc[i][j][r] = 0.f;

    const int grp = lane >> 3;
    const int li = lane & 7;
    uint32_t a_ro[2]; int a_sw[2];
    uint32_t b_ro[2]; int b_sw[2];
#pragma unroll
    for (int mi = 0; mi < 2; mi++) {
        const int r = wm + mi * 16 + li + (grp & 1) * 8;
        a_ro[mi] = r * 128;
        a_sw[mi] = (r & 7) << 4;
    }
#pragma unroll
    for (int nb = 0; nb < 2; nb++) {
        const int r = wn + nb * 16 + li + (grp >> 1) * 8;
        b_ro[nb] = r * 128;
        b_sw[nb] = (r & 7) << 4;
    }
    const int a_g16 = (grp >> 1) * 16;
    const int b_g16 = (grp & 1) * 16;

    const int nch = K >> 6;

#pragma unroll
    for (int s = 0; s < NSTG - 1; s++) {
#pragma unroll
        for (int i = 0; i < 2; i++) {
            const int cb = lcb0 + i * 16;
            cp16(arow + s * STG_B + (cb ^ lswz), Agb + s * 128 + cb);
            cp16(brow + s * STG_B + (cb ^ lswz), Wgb + s * 128 + cb);
        }
        cp_commit();
    }

    cp_wait<NSTG - 2>();
    __syncthreads();

    uint32_t af[2][2][4], bf[2][2][4];
#pragma unroll
    for (int mi = 0; mi < 2; mi++)
        ldsm4(af[0][mi], Asm + a_ro[mi] + (a_g16 ^ a_sw[mi]));
#pragma unroll
    for (int nb = 0; nb < 2; nb++)
        ldsm4(bf[0][nb], Bsm + b_ro[nb] + (b_g16 ^ b_sw[nb]));

    int buf = 0;
    for (int c = 0; c < nch; c++) {
        const uint32_t as = Asm + (c % NSTG) * STG_B;
        const uint32_t bs = Bsm + (c % NSTG) * STG_B;
        const uint32_t asn = Asm + ((c + 1) % NSTG) * STG_B;
        const uint32_t bsn = Bsm + ((c + 1) % NSTG) * STG_B;

#pragma unroll
        for (int ks = 0; ks < 4; ks++) {
            if (ks == 3) {
                cp_wait<NSTG - 2>();
                __syncthreads();
            }
            if (c < nch - 1 || ks < 3) {
                const uint32_t las = (ks < 3) ? as : asn;
                const uint32_t lbs = (ks < 3) ? bs : bsn;
                const int koff = ((ks + 1) & 3) * 32;
#pragma unroll
                for (int mi = 0; mi < 2; mi++)
                    ldsm4(af[buf ^ 1][mi], las + a_ro[mi] + ((koff + a_g16) ^ a_sw[mi]));
#pragma unroll
                for (int nb = 0; nb < 2; nb++)
                    ldsm4(bf[buf ^ 1][nb], lbs + b_ro[nb] + ((koff + b_g16) ^ b_sw[nb]));
            }
            if (ks == 0) {
                const int pf = c + NSTG - 1;
                if (pf < nch) {
                    const int s = pf % NSTG;
#pragma unroll
                    for (int i = 0; i < 2; i++) {
                        const int cb = lcb0 + i * 16;
                        cp16(arow + s * STG_B + (cb ^ lswz), Agb + (size_t)pf * 128 + cb);
                        cp16(brow + s * STG_B + (cb ^ lswz), Wgb + (size_t)pf * 128 + cb);
                    }
                }
                cp_commit();
            }
#pragma unroll
            for (int mi = 0; mi < 2; mi++)
#pragma unroll
                for (int ni = 0; ni < 4; ni++)
                    mma_f16(acc[mi][ni], af[buf][mi], &bf[buf][ni >> 1][(ni & 1) * 2]);
            buf ^= 1;
        }
    }

    const int g = lane >> 2;
    const int tg = lane & 3;

    if (EPI == 1) {
#pragma unroll
        for (int mi = 0; mi < 2; mi++) {
#pragma unroll
            for (int ni = 0; ni < 4; ni++) {
                const int row = m0 + wm + mi * 16 + g;
                const int col = n0 + wn + ni * 8 + tg * 2;
                float2 v0 = make_float2(acc[mi][ni][0], acc[mi][ni][1]);
                float2 v1 = make_float2(acc[mi][ni][2], acc[mi][ni][3]);
                const float2 r0 = *(const float2*)(res + (size_t)row * N + col);
                const float2 r1 = *(const float2*)(res + (size_t)(row + 8) * N + col);
                v0.x += r0.x; v0.y += r0.y;
                v1.x += r1.x; v1.y += r1.y;
                *(float2*)(C + (size_t)row * N + col) = v0;
                *(float2*)(C + (size_t)(row + 8) * N + col) = v1;
            }
        }
    } else {
        // ---- fused qkv epilogue: stage tile to smem, per-head norm+rope ----
        __syncthreads();
        float* sf = (float*)smem;  // [128][132]
#pragma unroll
        for (int mi = 0; mi < 2; mi++) {
#pragma unroll
            for (int ni = 0; ni < 4; ni++) {
                const int r = wm + mi * 16 + g;
                const int cl = wn + ni * 8 + tg * 2;
                *(float2*)&sf[r * 132 + cl] = make_float2(acc[mi][ni][0], acc[mi][ni][1]);
                *(float2*)&sf[(r + 8) * 132 + cl] = make_float2(acc[mi][ni][2], acc[mi][ni][3]);
            }
        }
        __syncthreads();

        const int gi = t >> 4;        // group 0..31
        const int tl = t & 15;
        const int j = tl * 2;
        const int hbase = n0 >> 6;

        for (int it = 0; it < 8; it++) {
            const int p = it * 32 + gi;   // 256 (row, head-in-tile) pairs
            const int r = p >> 1;
            const int hh = p & 1;
            const int head = hbase + hh;
            const int rowg = m0 + r;
            const int b = rowg >> 11;
            const int l = rowg & (LL - 1);
            const float* sr = &sf[r * 132 + hh * 64];

            const float a0 = sr[j], a1 = sr[j + 1];
            const float b0 = sr[j + 32], b1 = sr[j + 33];

            if (head < 20) {
                float ss = a0 * a0 + a1 * a1 + b0 * b0 + b1 * b1;
#pragma unroll
                for (int m = 8; m; m >>= 1)
                    ss += __shfl_xor_sync(0xffffffffu, ss, m, 16);
                const float inv = rsqrtf(ss * (1.0f / HD) + EPSV);
                const float4 rp = g_rope[l * 16 + tl];
                const float a0n = a0 * inv, a1n = a1 * inv;
                const float b0n = b0 * inv, b1n = b1 * inv;
                const float o0 = a0n * rp.x - b0n * rp.z;
                const float o1 = a1n * rp.y - b1n * rp.w;
                const float o2 = a0n * rp.z + b0n * rp.x;
                const float o3 = a1n * rp.w + b1n * rp.y;
                if (head < 16) {
                    const float sc = 0.125f;
                    __half* dq = g_qh + (((size_t)(b * NH + head)) * LL + l) * HD;
                    *(__half2*)(dq + j) = __floats2half2_rn(o0 * sc, o1 * sc);
                    *(__half2*)(dq + j + 32) = __floats2half2_rn(o2 * sc, o3 * sc);
                } else {
                    __half* dk = g_kh + (((size_t)(b * NKV + (head - 16))) * LL + l) * HD;
                    *(__half2*)(dk + j) = __floats2half2_rn(o0, o1);
                    *(__half2*)(dk + j + 32) = __floats2half2_rn(o2, o3);
                }
            } else {
                __half* dv = g_vh + (((size_t)(b * NKV + (head - 20))) * LL + l) * HD;
                *(__half2*)(dv + j) = __floats2half2_rn(a0, a1);
                *(__half2*)(dv + j + 32) = __floats2half2_rn(b0, b1);
            }
        }
    }
}

// ---------------- tensor-core flash attention: 128 q-rows, 8 warps ----------------
// Q tile 128x64 (16KB), K/V 64x64 double-buffered (4x8KB). smem 48KB.
#define ATT_SMEM (16384 + 4 * 8192)
__global__ void __launch_bounds__(256) attn_mma_kernel() {
    extern __shared__ char smc[];
    const uint32_t sb = smem_u32(smc);
    const uint32_t Qs = sb;                 // 16KB
    const uint32_t Ks = sb + 16384;         // 2 x 8KB
    const uint32_t Vs = sb + 32768;         // 2 x 8KB
    __shared__ int lo_s[128];

    const int qb = blockIdx.x, h = blockIdx.y, b = blockIdx.z;
    const int t = threadIdx.x;
    const int lane = t & 31;
    const int w = t >> 5;                   // 0..7
    const int q0 = qb * 128;
    const int kvh = h >> 2;
    const char* Qg = (const char*)(g_qh + (((size_t)(b * NH + h)) * LL + q0) * HD);
    const char* Kg = (const char*)(g_kh + ((size_t)(b * NKV + kvh)) * LL * HD);
    const char* Vg = (const char*)(g_vh + ((size_t)(b * NKV + kvh)) * LL * HD);

    const int kb0 = g_lo[b * LL + q0] & ~63;   // lo non-decreasing
    const int nt = ((q0 + 127 - kb0) >> 6) + 1;
    if (t < 128) lo_s[t] = g_lo[b * LL + q0 + t];

    // Q loader: row t/2, 4 x 16B at (t&1)*64
    const int lrQ = t >> 1;
    const int lcQ = (t & 1) * 64;
    const int lswQ = (lrQ & 7) << 4;
    // K/V loader: row t/4, 2 x 16B at (t&3)*32
    const int lrK = t >> 2;
    const int lcK = (t & 3) * 32;
    const int lswK = (lrK & 7) << 4;
    const uint32_t krow_s = Ks + lrK * 128;
    const uint32_t vrow_s = Vs + lrK * 128;

    // preload Q + tile 0 of K/V
#pragma unroll
    for (int i = 0; i < 4; i++) {
        const int cb = lcQ + i * 16;
        cp16(Qs + lrQ * 128 + (cb ^ lswQ), Qg + lrQ * 128 + cb);
    }
#pragma unroll
    for (int i = 0; i < 2; i++) {
        const int cb = lcK + i * 16;
        cp16(krow_s + (cb ^ lswK), Kg + (size_t)(kb0 + lrK) * 128 + cb);
        cp16(vrow_s + (cb ^ lswK), Vg + (size_t)(kb0 + lrK) * 128 + cb);
    }
    cp_commit();

    const int grp = lane >> 3;
    const int li = lane & 7;
    const int g = lane >> 2;
    const int tg = lane & 3;
    const int row0 = w * 16 + g;
    const int qg0 = q0 + row0;
    const int qg1 = qg0 + 8;

    cp_wait<0>();
    __syncthreads();

    uint32_t aQ[4][4];
    {
        const int qr = w * 16 + li + (grp & 1) * 8;
        const uint32_t qa = Qs + qr * 128;
        const int qsw = (qr & 7) << 4;
        const int qg16 = (grp >> 1) * 16;
#pragma unroll
        for (int kk = 0; kk < 4; kk++)
            ldsm4(aQ[kk], qa + ((kk * 32 + qg16) ^ qsw));
    }

    const int lo0 = lo_s[row0];
    const int lo1 = lo_s[row0 + 8];

    uint32_t k_ro[4]; int k_sw[4];
    uint32_t v_co[4];
#pragma unroll
    for (int nb = 0; nb < 4; nb++) {
        const int r = nb * 16 + li + (grp >> 1) * 8;
        k_ro[nb] = r * 128;
        k_sw[nb] = (r & 7) << 4;
        v_co[nb] = nb * 32 + (grp >> 1) * 16;
    }
    const int k_g16 = (grp & 1) * 16;
    const int v_r8 = (grp & 1) * 8 + li;

    float m0 = -1e30f, m1 = -1e30f, l0 = 0.f, l1 = 0.f;
    float o[8][4];
#pragma unroll
    for (int jn = 0; jn < 8; jn++)
#pragma unroll
        for (int r = 0; r < 4; r++) o[jn][r] = 0.f;

    for (int i = 0; i < nt; i++) {
        const int kb = kb0 + i * 64;
        if (i + 1 < nt) {
            const int bo = ((i + 1) & 1) * 8192;
            const size_t go = (size_t)(kb + 64 + lrK) * 128;
#pragma unroll
            for (int c2 = 0; c2 < 2; c2++) {
                const int cb = lcK + c2 * 16;
                cp16(krow_s + bo + (cb ^ lswK), Kg + go + cb);
                cp16(vrow_s + bo + (cb ^ lswK), Vg + go + cb);
            }
        }
        cp_commit();
        cp_wait<1>();
        __syncthreads();

        const uint32_t Kb = Ks + (i & 1) * 8192;
        const uint32_t Vb = Vs + (i & 1) * 8192;

        float sc[8][4];
#pragma unroll
        for (int j = 0; j < 8; j++)
#pragma unroll
            for (int r = 0; r < 4; r++) sc[j][r] = 0.f;

#pragma unroll
        for (int kk = 0; kk < 4; kk++) {
            uint32_t bfr[4][4];
#pragma unroll
            for (int nb = 0; nb < 4; nb++)
                ldsm4(bfr[nb], Kb + k_ro[nb] + ((kk * 32 + k_g16) ^ k_sw[nb]));
#pragma unroll
            for (int j = 0; j < 8; j++)
                mma_f16(sc[j], aQ[kk], &bfr[j >> 1][(j & 1) * 2]);
        }

        float mx0 = -1e30f, mx1 = -1e30f;
#pragma unroll
        for (int j = 0; j < 8; j++) {
            const int c0 = kb + j * 8 + tg * 2;
            const int c1 = c0 + 1;
            if (c0 < lo0 || c0 > qg0) sc[j][0] = -1e30f;
            if (c1 < lo0 || c1 > qg0) sc[j][1] = -1e30f;
            if (c0 < lo1 || c0 > qg1) sc[j][2] = -1e30f;
            if (c1 < lo1 || c1 > qg1) sc[j][3] = -1e30f;
            mx0 = fmaxf(mx0, fmaxf(sc[j][0], sc[j][1]));
            mx1 = fmaxf(mx1, fmaxf(sc[j][2], sc[j][3]));
        }
        mx0 = fmaxf(mx0, __shfl_xor_sync(0xffffffffu, mx0, 1));
        mx0 = fmaxf(mx0, __shfl_xor_sync(0xffffffffu, mx0, 2));
        mx1 = fmaxf(mx1, __shfl_xor_sync(0xffffffffu, mx1, 1));
        mx1 = fmaxf(mx1, __shfl_xor_sync(0xffffffffu, mx1, 2));

        const float mn0 = fmaxf(m0, mx0);
        const float mn1 = fmaxf(m1, mx1);
        const float al0 = __expf(m0 - mn0);
        const float al1 = __expf(m1 - mn1);

        float lp0 = 0.f, lp1 = 0.f;
        uint32_t ph[8][2];
#pragma unroll
        for (int j = 0; j < 8; j++) {
            const float p0 = (sc[j][0] > -1e29f) ? __expf(sc[j][0] - mn0) : 0.f;
            const float p1 = (sc[j][1] > -1e29f) ? __expf(sc[j][1] - mn0) : 0.f;
            const float p2 = (sc[j][2] > -1e29f) ? __expf(sc[j][2] - mn1) : 0.f;
            const float p3 = (sc[j][3] > -1e29f) ? __expf(sc[j][3] - mn1) : 0.f;
            lp0 += p0 + p1;
            lp1 += p2 + p3;
            __half2 h0 = __floats2half2_rn(p0, p1);
            __half2 h1 = __floats2half2_rn(p2, p3);
            ph[j][0] = *(uint32_t*)&h0;
            ph[j][1] = *(uint32_t*)&h1;
        }
        lp0 += __shfl_xor_sync(0xffffffffu, lp0, 1);
        lp0 += __shfl_xor_sync(0xffffffffu, lp0, 2);
        lp1 += __shfl_xor_sync(0xffffffffu, lp1, 1);
        lp1 += __shfl_xor_sync(0xffffffffu, lp1, 2);

        l0 = l0 * al0 + lp0;
        l1 = l1 * al1 + lp1;
        m0 = mn0; m1 = mn1;
#pragma unroll
        for (int jn = 0; jn < 8; jn++) {
            o[jn][0] *= al0; o[jn][1] *= al0;
            o[jn][2] *= al1; o[jn][3] *= al1;
        }

#pragma unroll
        for (int kk = 0; kk < 4; kk++) {
            uint32_t vf[4][4];
            const int vr = kk * 16 + v_r8;
            const uint32_t va = Vb + vr * 128;
            const int vsw = (vr & 7) << 4;
#pragma unroll
            for (int nb = 0; nb < 4; nb++)
                ldsm4t(vf[nb], va + (v_co[nb] ^ vsw));
            uint32_t aP[4] = { ph[2 * kk][0], ph[2 * kk][1],
                               ph[2 * kk + 1][0], ph[2 * kk + 1][1] };
#pragma unroll
            for (int jn = 0; jn < 8; jn++)
                mma_f16(o[jn], aP, &vf[jn >> 1][(jn & 1) * 2]);
        }
        __syncthreads();
    }

    const float iv0 = 1.0f / l0;
    const float iv1 = 1.0f / l1;
    __half* y0 = g_yh + ((size_t)(b * LL) + qg0) * DD + h * HD;
    __half* y1 = g_yh + ((size_t)(b * LL) + qg1) * DD + h * HD;
#pragma unroll
    for (int jn = 0; jn < 8; jn++) {
        __half2 r0 = __floats2half2_rn(o[jn][0] * iv0, o[jn][1] * iv0);
        __half2 r1 = __floats2half2_rn(o[jn][2] * iv1, o[jn][3] * iv1);
        *(__half2*)(y0 + jn * 8 + tg * 2) = r0;
        *(__half2*)(y1 + jn * 8 + tg * 2) = r1;
    }
}

// ---------------- launch ----------------
extern "C" void kernel_launch(void* const* d_in, const int* in_sizes, int n_in,
                              void* d_out, int out_size) {
    const float* x     = (const float*)d_in[0];
    const float* w_qkv = (const float*)d_in[1];
    const float* w_out = (const float*)d_in[2];
    const void*  mask  = d_in[3];
    float* out = (float*)d_out;

    __half *phh, *pwqh, *pwoh, *pyh;
    cudaGetSymbolAddress((void**)&phh, g_hh);
    cudaGetSymbolAddress((void**)&pwqh, g_wqkvh);
    cudaGetSymbolAddress((void**)&pwoh, g_wouth);
    cudaGetSymbolAddress((void**)&pyh, g_yh);

    const int M = BB * LL;

    cudaFuncSetAttribute(hgemm_kernel<1>,
                         cudaFuncAttributeMaxDynamicSharedMemorySize, GSMEM);
    cudaFuncSetAttribute(hgemm_kernel<2>,
                         cudaFuncAttributeMaxDynamicSharedMemorySize, GSMEM);
    cudaFuncSetAttribute(attn_mma_kernel,
                         cudaFuncAttributeMaxDynamicSharedMemorySize, ATT_SMEM);

    prep_kernel<<<NB_TOT, 256>>>(x, w_qkv, w_out, mask);

    hgemm_kernel<2><<<dim3(QKV_DIM / 128, M / 128), 512, GSMEM>>>(
        phh, pwqh, nullptr, nullptr, M, QKV_DIM, DD);

    attn_mma_kernel<<<dim3(LL / 128, NH, BB), 256, ATT_SMEM>>>();

    hgemm_kernel<1><<<dim3(DD / 128, M / 128), 512, GSMEM>>>(
        pyh, pwoh, x, out, M, DD, DD);
}

// round 15
// speedup vs baseline: 1.1883x; 1.0474x over previous
#include <cuda_runtime.h>
#include <cuda_fp16.h>
#include <math.h>
#include <stdint.h>

#define BB 2
#define LL 2048
#define DD 1024
#define NH 16
#define NKV 4
#define HD 64
#define WIN 1024
#define QKV_DIM 1536
#define EPSV 1.1920929e-07f

// ---------------- scratch (no cudaMalloc allowed) ----------------
__device__ __half g_hh[BB * LL * DD];
__device__ __half g_wqkvh[QKV_DIM * DD];
__device__ __half g_wouth[DD * DD];
__device__ __half g_yh[BB * LL * DD];
__device__ __half g_qh[BB * NH * LL * HD];
__device__ __half g_kh[BB * NKV * LL * HD];
__device__ __half g_vh[BB * NKV * LL * HD];
__device__ int    g_lo[BB * LL];
__device__ float4 g_rope[LL * 16];

// ---------------- ptx helpers ----------------
__device__ __forceinline__ uint32_t smem_u32(const void* p) {
    uint32_t a;
    asm("{ .reg .u64 t; cvta.to.shared.u64 t, %1; cvt.u32.u64 %0, t; }"
        : "=r"(a) : "l"(p));
    return a;
}
__device__ __forceinline__ void cp16(uint32_t smem_dst, const void* gsrc) {
    asm volatile("cp.async.cg.shared.global [%0], [%1], 16;\n"
                 :: "r"(smem_dst), "l"(gsrc));
}
__device__ __forceinline__ void cp_commit() {
    asm volatile("cp.async.commit_group;\n");
}
template <int N>
__device__ __forceinline__ void cp_wait() {
    asm volatile("cp.async.wait_group %0;\n" :: "n"(N));
}
__device__ __forceinline__ void ldsm4(uint32_t* r, uint32_t addr) {
    asm volatile("ldmatrix.sync.aligned.m8n8.x4.shared.b16 {%0,%1,%2,%3}, [%4];"
                 : "=r"(r[0]), "=r"(r[1]), "=r"(r[2]), "=r"(r[3]) : "r"(addr));
}
__device__ __forceinline__ void ldsm4t(uint32_t* r, uint32_t addr) {
    asm volatile("ldmatrix.sync.aligned.m8n8.x4.trans.shared.b16 {%0,%1,%2,%3}, [%4];"
                 : "=r"(r[0]), "=r"(r[1]), "=r"(r[2]), "=r"(r[3]) : "r"(addr));
}
__device__ __forceinline__ void mma_f16(float* c, const uint32_t* a, const uint32_t* b) {
    asm volatile(
        "mma.sync.aligned.m16n8k16.row.col.f32.f16.f16.f32 "
        "{%0,%1,%2,%3}, {%4,%5,%6,%7}, {%8,%9}, {%0,%1,%2,%3};"
        : "+f"(c[0]), "+f"(c[1]), "+f"(c[2]), "+f"(c[3])
        : "r"(a[0]), "r"(a[1]), "r"(a[2]), "r"(a[3]), "r"(b[0]), "r"(b[1]));
}

// ---------------- fused prep kernel ----------------
#define NB_SEG  BB
#define NB_ROPE 128
#define NB_CONV 2560
#define NB_RMS  (BB * LL)
#define NB_TOT  (NB_SEG + NB_ROPE + NB_CONV + NB_RMS)

__global__ void __launch_bounds__(256) prep_kernel(
    const float* __restrict__ x, const float* __restrict__ wq,
    const float* __restrict__ wo, const void* __restrict__ mask)
{
    const int bid = blockIdx.x;
    const int t = threadIdx.x;

    if (bid < NB_SEG) {
        __shared__ int sA[256];
        __shared__ int sB[256];
        __shared__ int encs;
        const int b = bid;
        if (t == 0) {
            const unsigned* mi = (const unsigned*)mask;
            int e = 0;
            for (int i = 0; i < 64; i++) {
                unsigned v = mi[i];
                if (v == 0x3F800000u) { e = 2; break; }
                if (v > 1u) e = 1;
            }
            encs = e;
        }
        __syncthreads();
        const int e = encs;

        int pref[8];
        int run = 0;
        const int base = t * 8;
#pragma unroll
        for (int i = 0; i < 8; i++) {
            const int idx = base + i;
            int mset;
            if (e == 0)      mset = ((const int*)mask)[b * LL + idx] != 0;
            else if (e == 1) mset = ((const unsigned char*)mask)[b * LL + idx] != 0;
            else             mset = ((const float*)mask)[b * LL + idx] != 0.0f;
            run = max(run, mset ? idx : 0);
            pref[i] = run;
        }
        sA[t] = run;
        __syncthreads();
        int* s = sA;
        int* d = sB;
        for (int off = 1; off < 256; off <<= 1) {
            int v = s[t];
            if (t >= off) v = max(v, s[t - off]);
            d[t] = v;
            __syncthreads();
            int* tmp = s; s = d; d = tmp;
        }
        const int excl = (t > 0) ? s[t - 1] : 0;
#pragma unroll
        for (int i = 0; i < 8; i++) {
            const int idx = base + i;
            g_lo[b * LL + idx] = max(idx - (WIN - 1), max(excl, pref[i]));
        }
    } else if (bid < NB_SEG + NB_ROPE) {
        const int i = (bid - NB_SEG) * 256 + t;
        const int l = i >> 4;
        const int j = (i & 15) * 2;
        const float lg = logf(10000.0f) * (1.0f / 32.0f);
        const float f0 = expf(-lg * (float)j);
        const float f1 = expf(-lg * (float)(j + 1));
        float s0, c0, s1, c1;
        sincosf((float)l * f0, &s0, &c0);
        sincosf((float)l * f1, &s1, &c1);
        g_rope[i] = make_float4(c0, c1, s0, s1);
    } else if (bid < NB_SEG + NB_ROPE + NB_CONV) {
        const int n1 = QKV_DIM * DD;
        const int i = ((bid - NB_SEG - NB_ROPE) * 256 + t) * 4;
        if (i < n1) {
            float4 v = *(const float4*)(wq + i);
            *(__half2*)(g_wqkvh + i) = __floats2half2_rn(v.x, v.y);
            *(__half2*)(g_wqkvh + i + 2) = __floats2half2_rn(v.z, v.w);
        } else {
            const int k = i - n1;
            float4 v = *(const float4*)(wo + k);
            *(__half2*)(g_wouth + k) = __floats2half2_rn(v.x, v.y);
            *(__half2*)(g_wouth + k + 2) = __floats2half2_rn(v.z, v.w);
        }
    } else {
        const int row = bid - (NB_SEG + NB_ROPE + NB_CONV);
        const float4* xr = (const float4*)(x + (size_t)row * DD);
        __half2* hr = (__half2*)(g_hh + (size_t)row * DD);
        const float4 v = xr[t];
        float ss = v.x * v.x + v.y * v.y + v.z * v.z + v.w * v.w;

        __shared__ float red[8];
#pragma unroll
        for (int m = 16; m; m >>= 1) ss += __shfl_xor_sync(0xffffffffu, ss, m);
        if ((t & 31) == 0) red[t >> 5] = ss;
        __syncthreads();
        if (t < 8) {
            float r = red[t];
#pragma unroll
            for (int m = 4; m; m >>= 1) r += __shfl_xor_sync(0xffu, r, m, 8);
            if (t == 0) red[0] = r;
        }
        __syncthreads();
        const float inv = rsqrtf(red[0] * (1.0f / DD) + EPSV);
        hr[t * 2] = __floats2half2_rn(v.x * inv, v.y * inv);
        hr[t * 2 + 1] = __floats2half2_rn(v.z * inv, v.w * inv);
    }
}

// ---------------- fp16 mma.sync GEMM: 512 threads, 16 warps (4/SMSP) ----------------
// ROUND-10 VERIFIED CONFIG. 128x128 tile, BK=64, NSTG=4 (128KB smem, 1 CTA/SM).
#define NSTG 4
#define STG_B (128 * 128)
#define GSMEM (2 * NSTG * STG_B)

template <int EPI>
__global__ void __launch_bounds__(512) hgemm_kernel(
    const __half* __restrict__ A, const __half* __restrict__ W,
    const float* __restrict__ res, float* __restrict__ C,
    int M, int N, int K)
{
    extern __shared__ char smem[];
    const uint32_t sb = smem_u32(smem);
    const uint32_t Asm = sb;
    const uint32_t Bsm = sb + NSTG * STG_B;

    const int t = threadIdx.x;
    const int lane = t & 31;
    const int wid = t >> 5;
    const int wm = (wid & 3) * 32;
    const int wn = (wid >> 2) * 32;
    const int m0 = blockIdx.y * 128;
    const int n0 = blockIdx.x * 128;

    const int lrow = t >> 2;
    const int lcb0 = (t & 3) * 32;
    const int lswz = (lrow & 7) << 4;
    const char* Agb = (const char*)(A + (size_t)(m0 + lrow) * K);
    const char* Wgb = (const char*)(W + (size_t)(n0 + lrow) * K);
    const uint32_t arow = Asm + lrow * 128;
    const uint32_t brow = Bsm + lrow * 128;

    float acc[2][4][4];
#pragma unroll
    for (int i = 0; i < 2; i++)
#pragma unroll
        for (int j = 0; j < 4; j++)
#pragma unroll
            for (int r = 0; r < 4; r++) acc[i][j][r] = 0.f;

    const int grp = lane >> 3;
    const int li = lane & 7;
    uint32_t a_ro[2]; int a_sw[2];
    uint32_t b_ro[2]; int b_sw[2];
#pragma unroll
    for (int mi = 0; mi < 2; mi++) {
        const int r = wm + mi * 16 + li + (grp & 1) * 8;
        a_ro[mi] = r * 128;
        a_sw[mi] = (r & 7) << 4;
    }
#pragma unroll
    for (int nb = 0; nb < 2; nb++) {
        const int r = wn + nb * 16 + li + (grp >> 1) * 8;
        b_ro[nb] = r * 128;
        b_sw[nb] = (r & 7) << 4;
    }
    const int a_g16 = (grp >> 1) * 16;
    const int b_g16 = (grp & 1) * 16;

    const int nch = K >> 6;

#pragma unroll
    for (int s = 0; s < NSTG - 1; s++) {
#pragma unroll
        for (int i = 0; i < 2; i++) {
            const int cb = lcb0 + i * 16;
            cp16(arow + s * STG_B + (cb ^ lswz), Agb + s * 128 + cb);
            cp16(brow + s * STG_B + (cb ^ lswz), Wgb + s * 128 + cb);
        }
        cp_commit();
    }

    cp_wait<NSTG - 2>();
    __syncthreads();

    uint32_t af[2][2][4], bf[2][2][4];
#pragma unroll
    for (int mi = 0; mi < 2; mi++)
        ldsm4(af[0][mi], Asm + a_ro[mi] + (a_g16 ^ a_sw[mi]));
#pragma unroll
    for (int nb = 0; nb < 2; nb++)
        ldsm4(bf[0][nb], Bsm + b_ro[nb] + (b_g16 ^ b_sw[nb]));

    int buf = 0;
    for (int c = 0; c < nch; c++) {
        const uint32_t as = Asm + (c % NSTG) * STG_B;
        const uint32_t bs = Bsm + (c % NSTG) * STG_B;
        const uint32_t asn = Asm + ((c + 1) % NSTG) * STG_B;
        const uint32_t bsn = Bsm + ((c + 1) % NSTG) * STG_B;

#pragma unroll
        for (int ks = 0; ks < 4; ks++) {
            if (ks == 3) {
                cp_wait<NSTG - 2>();
                __syncthreads();
            }
            if (c < nch - 1 || ks < 3) {
                const uint32_t las = (ks < 3) ? as : asn;
                const uint32_t lbs = (ks < 3) ? bs : bsn;
                const int koff = ((ks + 1) & 3) * 32;
#pragma unroll
                for (int mi = 0; mi < 2; mi++)
                    ldsm4(af[buf ^ 1][mi], las + a_ro[mi] + ((koff + a_g16) ^ a_sw[mi]));
#pragma unroll
                for (int nb = 0; nb < 2; nb++)
                    ldsm4(bf[buf ^ 1][nb], lbs + b_ro[nb] + ((koff + b_g16) ^ b_sw[nb]));
            }
            if (ks == 0) {
                const int pf = c + NSTG - 1;
                if (pf < nch) {
                    const int s = pf % NSTG;
#pragma unroll
                    for (int i = 0; i < 2; i++) {
                        const int cb = lcb0 + i * 16;
                        cp16(arow + s * STG_B + (cb ^ lswz), Agb + (size_t)pf * 128 + cb);
                        cp16(brow + s * STG_B + (cb ^ lswz), Wgb + (size_t)pf * 128 + cb);
                    }
                }
                cp_commit();
            }
#pragma unroll
            for (int mi = 0; mi < 2; mi++)
#pragma unroll
                for (int ni = 0; ni < 4; ni++)
                    mma_f16(acc[mi][ni], af[buf][mi], &bf[buf][ni >> 1][(ni & 1) * 2]);
            buf ^= 1;
        }
    }

    const int g = lane >> 2;
    const int tg = lane & 3;

    if (EPI == 1) {
#pragma unroll
        for (int mi = 0; mi < 2; mi++) {
#pragma unroll
            for (int ni = 0; ni < 4; ni++) {
                const int row = m0 + wm + mi * 16 + g;
                const int col = n0 + wn + ni * 8 + tg * 2;
                float2 v0 = make_float2(acc[mi][ni][0], acc[mi][ni][1]);
                float2 v1 = make_float2(acc[mi][ni][2], acc[mi][ni][3]);
                const float2 r0 = *(const float2*)(res + (size_t)row * N + col);
                const float2 r1 = *(const float2*)(res + (size_t)(row + 8) * N + col);
                v0.x += r0.x; v0.y += r0.y;
                v1.x += r1.x; v1.y += r1.y;
                *(float2*)(C + (size_t)row * N + col) = v0;
                *(float2*)(C + (size_t)(row + 8) * N + col) = v1;
            }
        }
    } else {
        __syncthreads();
        float* sf = (float*)smem;  // [128][132]
#pragma unroll
        for (int mi = 0; mi < 2; mi++) {
#pragma unroll
            for (int ni = 0; ni < 4; ni++) {
                const int r = wm + mi * 16 + g;
                const int cl = wn + ni * 8 + tg * 2;
                *(float2*)&sf[r * 132 + cl] = make_float2(acc[mi][ni][0], acc[mi][ni][1]);
                *(float2*)&sf[(r + 8) * 132 + cl] = make_float2(acc[mi][ni][2], acc[mi][ni][3]);
            }
        }
        __syncthreads();

        const int gi = t >> 4;
        const int tl = t & 15;
        const int j = tl * 2;
        const int hbase = n0 >> 6;

        for (int it = 0; it < 8; it++) {
            const int p = it * 32 + gi;
            const int r = p >> 1;
            const int hh = p & 1;
            const int head = hbase + hh;
            const int rowg = m0 + r;
            const int b = rowg >> 11;
            const int l = rowg & (LL - 1);
            const float* sr = &sf[r * 132 + hh * 64];

            const float a0 = sr[j], a1 = sr[j + 1];
            const float b0 = sr[j + 32], b1 = sr[j + 33];

            if (head < 20) {
                float ss = a0 * a0 + a1 * a1 + b0 * b0 + b1 * b1;
#pragma unroll
                for (int m = 8; m; m >>= 1)
                    ss += __shfl_xor_sync(0xffffffffu, ss, m, 16);
                const float inv = rsqrtf(ss * (1.0f / HD) + EPSV);
                const float4 rp = g_rope[l * 16 + tl];
                const float a0n = a0 * inv, a1n = a1 * inv;
                const float b0n = b0 * inv, b1n = b1 * inv;
                const float o0 = a0n * rp.x - b0n * rp.z;
                const float o1 = a1n * rp.y - b1n * rp.w;
                const float o2 = a0n * rp.z + b0n * rp.x;
                const float o3 = a1n * rp.w + b1n * rp.y;
                if (head < 16) {
                    const float sc = 0.125f;
                    __half* dq = g_qh + (((size_t)(b * NH + head)) * LL + l) * HD;
                    *(__half2*)(dq + j) = __floats2half2_rn(o0 * sc, o1 * sc);
                    *(__half2*)(dq + j + 32) = __floats2half2_rn(o2 * sc, o3 * sc);
                } else {
                    __half* dk = g_kh + (((size_t)(b * NKV + (head - 16))) * LL + l) * HD;
                    *(__half2*)(dk + j) = __floats2half2_rn(o0, o1);
                    *(__half2*)(dk + j + 32) = __floats2half2_rn(o2, o3);
                }
            } else {
                __half* dv = g_vh + (((size_t)(b * NKV + (head - 20))) * LL + l) * HD;
                *(__half2*)(dv + j) = __floats2half2_rn(a0, a1);
                *(__half2*)(dv + j + 32) = __floats2half2_rn(b0, b1);
            }
        }
    }
}

// ---------------- tensor-core flash attention: 2 heads/CTA sharing K/V ----------------
// 256 threads: warps 0-3 head 2y, warps 4-7 head 2y+1 (same kv group).
// Q: 2 x 64x64 (16KB), K/V 64x64 double-buffered (4 x 8KB). smem 48KB.
#define ATT_SMEM (16384 + 4 * 8192)
__global__ void __launch_bounds__(256) attn_mma_kernel() {
    extern __shared__ char smc[];
    const uint32_t sb = smem_u32(smc);
    const uint32_t Qs = sb;                 // 2 x 8KB (per head)
    const uint32_t Ks = sb + 16384;         // 2 x 8KB
    const uint32_t Vs = sb + 32768;         // 2 x 8KB
    __shared__ int lo_s[64];

    const int qb = blockIdx.x, hp = blockIdx.y, b = blockIdx.z;
    const int t = threadIdx.x;
    const int lane = t & 31;
    const int w = t >> 5;                   // 0..7
    const int wg = w >> 2;                  // head select
    const int wl = w & 3;                   // warp within head
    const int q0 = qb * 64;
    const int h = hp * 2 + wg;
    const int kvh = hp >> 1;
    const char* Kg = (const char*)(g_kh + ((size_t)(b * NKV + kvh)) * LL * HD);
    const char* Vg = (const char*)(g_vh + ((size_t)(b * NKV + kvh)) * LL * HD);

    const int kb0 = g_lo[b * LL + q0] & ~63;
    const int nt = ((q0 + 63 - kb0) >> 6) + 1;
    if (t < 64) lo_s[t] = g_lo[b * LL + q0 + t];

    // Q loader: 128 rows (2 heads x 64), row t/2, 4 x 16B at (t&1)*64
    {
        const int lr = t >> 1;
        const int hh = lr >> 6;             // which head's rows
        const int qr = lr & 63;
        const int lsw = (qr & 7) << 4;
        const char* Qg = (const char*)(g_qh +
            (((size_t)(b * NH + hp * 2 + hh)) * LL + q0 + qr) * HD);
        const uint32_t qdst = Qs + hh * 8192 + qr * 128;
#pragma unroll
        for (int i = 0; i < 4; i++) {
            const int cb = (t & 1) * 64 + i * 16;
            cp16(qdst + (cb ^ lsw), Qg + cb);
        }
    }
    // K/V loader: row t/4, 2 x 16B at (t&3)*32
    const int lrK = t >> 2;
    const int lcK = (t & 3) * 32;
    const int lswK = (lrK & 7) << 4;
    const uint32_t krow_s = Ks + lrK * 128;
    const uint32_t vrow_s = Vs + lrK * 128;
#pragma unroll
    for (int i = 0; i < 2; i++) {
        const int cb = lcK + i * 16;
        cp16(krow_s + (cb ^ lswK), Kg + (size_t)(kb0 + lrK) * 128 + cb);
        cp16(vrow_s + (cb ^ lswK), Vg + (size_t)(kb0 + lrK) * 128 + cb);
    }
    cp_commit();

    const int grp = lane >> 3;
    const int li = lane & 7;
    const int g = lane >> 2;
    const int tg = lane & 3;
    const int row0 = wl * 16 + g;
    const int qg0 = q0 + row0;
    const int qg1 = qg0 + 8;

    cp_wait<0>();
    __syncthreads();

    uint32_t aQ[4][4];
    {
        const int qr = wl * 16 + li + (grp & 1) * 8;
        const uint32_t qa = Qs + wg * 8192 + qr * 128;
        const int qsw = (qr & 7) << 4;
        const int qg16 = (grp >> 1) * 16;
#pragma unroll
        for (int kk = 0; kk < 4; kk++)
            ldsm4(aQ[kk], qa + ((kk * 32 + qg16) ^ qsw));
    }

    const int lo0 = lo_s[row0];
    const int lo1 = lo_s[row0 + 8];

    uint32_t k_ro[4]; int k_sw[4];
    uint32_t v_co[4];
#pragma unroll
    for (int nb = 0; nb < 4; nb++) {
        const int r = nb * 16 + li + (grp >> 1) * 8;
        k_ro[nb] = r * 128;
        k_sw[nb] = (r & 7) << 4;
        v_co[nb] = nb * 32 + (grp >> 1) * 16;
    }
    const int k_g16 = (grp & 1) * 16;
    const int v_r8 = (grp & 1) * 8 + li;

    float m0 = -1e30f, m1 = -1e30f, l0 = 0.f, l1 = 0.f;
    float o[8][4];
#pragma unroll
    for (int jn = 0; jn < 8; jn++)
#pragma unroll
        for (int r = 0; r < 4; r++) o[jn][r] = 0.f;

    for (int i = 0; i < nt; i++) {
        const int kb = kb0 + i * 64;
        if (i + 1 < nt) {
            const int bo = ((i + 1) & 1) * 8192;
            const size_t go = (size_t)(kb + 64 + lrK) * 128;
#pragma unroll
            for (int c2 = 0; c2 < 2; c2++) {
                const int cb = lcK + c2 * 16;
                cp16(krow_s + bo + (cb ^ lswK), Kg + go + cb);
                cp16(vrow_s + bo + (cb ^ lswK), Vg + go + cb);
            }
        }
        cp_commit();
        cp_wait<1>();
        __syncthreads();

        const uint32_t Kb = Ks + (i & 1) * 8192;
        const uint32_t Vb = Vs + (i & 1) * 8192;

        float sc[8][4];
#pragma unroll
        for (int j = 0; j < 8; j++)
#pragma unroll
            for (int r = 0; r < 4; r++) sc[j][r] = 0.f;

#pragma unroll
        for (int kk = 0; kk < 4; kk++) {
            uint32_t bfr[4][4];
#pragma unroll
            for (int nb = 0; nb < 4; nb++)
                ldsm4(bfr[nb], Kb + k_ro[nb] + ((kk * 32 + k_g16) ^ k_sw[nb]));
#pragma unroll
            for (int j = 0; j < 8; j++)
                mma_f16(sc[j], aQ[kk], &bfr[j >> 1][(j & 1) * 2]);
        }

        float mx0 = -1e30f, mx1 = -1e30f;
#pragma unroll
        for (int j = 0; j < 8; j++) {
            const int c0 = kb + j * 8 + tg * 2;
            const int c1 = c0 + 1;
            if (c0 < lo0 || c0 > qg0) sc[j][0] = -1e30f;
            if (c1 < lo0 || c1 > qg0) sc[j][1] = -1e30f;
            if (c0 < lo1 || c0 > qg1) sc[j][2] = -1e30f;
            if (c1 < lo1 || c1 > qg1) sc[j][3] = -1e30f;
            mx0 = fmaxf(mx0, fmaxf(sc[j][0], sc[j][1]));
            mx1 = fmaxf(mx1, fmaxf(sc[j][2], sc[j][3]));
        }
        mx0 = fmaxf(mx0, __shfl_xor_sync(0xffffffffu, mx0, 1));
        mx0 = fmaxf(mx0, __shfl_xor_sync(0xffffffffu, mx0, 2));
        mx1 = fmaxf(mx1, __shfl_xor_sync(0xffffffffu, mx1, 1));
        mx1 = fmaxf(mx1, __shfl_xor_sync(0xffffffffu, mx1, 2));

        const float mn0 = fmaxf(m0, mx0);
        const float mn1 = fmaxf(m1, mx1);
        const float al0 = __expf(m0 - mn0);
        const float al1 = __expf(m1 - mn1);

        float lp0 = 0.f, lp1 = 0.f;
        uint32_t ph[8][2];
#pragma unroll
        for (int j = 0; j < 8; j++) {
            const float p0 = (sc[j][0] > -1e29f) ? __expf(sc[j][0] - mn0) : 0.f;
            const float p1 = (sc[j][1] > -1e29f) ? __expf(sc[j][1] - mn0) : 0.f;
            const float p2 = (sc[j][2] > -1e29f) ? __expf(sc[j][2] - mn1) : 0.f;
            const float p3 = (sc[j][3] > -1e29f) ? __expf(sc[j][3] - mn1) : 0.f;
            lp0 += p0 + p1;
            lp1 += p2 + p3;
            __half2 h0 = __floats2half2_rn(p0, p1);
            __half2 h1 = __floats2half2_rn(p2, p3);
            ph[j][0] = *(uint32_t*)&h0;
            ph[j][1] = *(uint32_t*)&h1;
        }
        lp0 += __shfl_xor_sync(0xffffffffu, lp0, 1);
        lp0 += __shfl_xor_sync(0xffffffffu, lp0, 2);
        lp1 += __shfl_xor_sync(0xffffffffu, lp1, 1);
        lp1 += __shfl_xor_sync(0xffffffffu, lp1, 2);

        l0 = l0 * al0 + lp0;
        l1 = l1 * al1 + lp1;
        m0 = mn0; m1 = mn1;
#pragma unroll
        for (int jn = 0; jn < 8; jn++) {
            o[jn][0] *= al0; o[jn][1] *= al0;
            o[jn][2] *= al1; o[jn][3] *= al1;
        }

#pragma unroll
        for (int kk = 0; kk < 4; kk++) {
            uint32_t vf[4][4];
            const int vr = kk * 16 + v_r8;
            const uint32_t va = Vb + vr * 128;
            const int vsw = (vr & 7) << 4;
#pragma unroll
            for (int nb = 0; nb < 4; nb++)
                ldsm4t(vf[nb], va + (v_co[nb] ^ vsw));
            uint32_t aP[4] = { ph[2 * kk][0], ph[2 * kk][1],
                               ph[2 * kk + 1][0], ph[2 * kk + 1][1] };
#pragma unroll
            for (int jn = 0; jn < 8; jn++)
                mma_f16(o[jn], aP, &vf[jn >> 1][(jn & 1) * 2]);
        }
        __syncthreads();
    }

    const float iv0 = 1.0f / l0;
    const float iv1 = 1.0f / l1;
    __half* y0 = g_yh + ((size_t)(b * LL) + qg0) * DD + h * HD;
    __half* y1 = g_yh + ((size_t)(b * LL) + qg1) * DD + h * HD;
#pragma unroll
    for (int jn = 0; jn < 8; jn++) {
        __half2 r0 = __floats2half2_rn(o[jn][0] * iv0, o[jn][1] * iv0);
        __half2 r1 = __floats2half2_rn(o[jn][2] * iv1, o[jn][3] * iv1);
        *(__half2*)(y0 + jn * 8 + tg * 2) = r0;
        *(__half2*)(y1 + jn * 8 + tg * 2) = r1;
    }
}

// ---------------- launch ----------------
extern "C" void kernel_launch(void* const* d_in, const int* in_sizes, int n_in,
                              void* d_out, int out_size) {
    const float* x     = (const float*)d_in[0];
    const float* w_qkv = (const float*)d_in[1];
    const float* w_out = (const float*)d_in[2];
    const void*  mask  = d_in[3];
    float* out = (float*)d_out;

    __half *phh, *pwqh, *pwoh, *pyh;
    cudaGetSymbolAddress((void**)&phh, g_hh);
    cudaGetSymbolAddress((void**)&pwqh, g_wqkvh);
    cudaGetSymbolAddress((void**)&pwoh, g_wouth);
    cudaGetSymbolAddress((void**)&pyh, g_yh);

    const int M = BB * LL;

    cudaFuncSetAttribute(hgemm_kernel<1>,
                         cudaFuncAttributeMaxDynamicSharedMemorySize, GSMEM);
    cudaFuncSetAttribute(hgemm_kernel<2>,
                         cudaFuncAttributeMaxDynamicSharedMemorySize, GSMEM);
    cudaFuncSetAttribute(attn_mma_kernel,
                         cudaFuncAttributeMaxDynamicSharedMemorySize, ATT_SMEM);

    prep_kernel<<<NB_TOT, 256>>>(x, w_qkv, w_out, mask);

    hgemm_kernel<2><<<dim3(QKV_DIM / 128, M / 128), 512, GSMEM>>>(
        phh, pwqh, nullptr, nullptr, M, QKV_DIM, DD);

    attn_mma_kernel<<<dim3(LL / 64, NH / 2, BB), 256, ATT_SMEM>>>();

    hgemm_kernel<1><<<dim3(DD / 128, M / 128), 512, GSMEM>>>(
        pyh, pwoh, x, out, M, DD, DD);
}

// round 16
// speedup vs baseline: 1.2114x; 1.0195x over previous
#include <cuda_runtime.h>
#include <cuda_fp16.h>
#include <math.h>
#include <stdint.h>

#define BB 2
#define LL 2048
#define DD 1024
#define NH 16
#define NKV 4
#define HD 64
#define WIN 1024
#define QKV_DIM 1536
#define EPSV 1.1920929e-07f

// ---------------- scratch (no cudaMalloc allowed) ----------------
__device__ __half g_hh[BB * LL * DD];
__device__ __half g_wqkvh[QKV_DIM * DD];
__device__ __half g_wouth[DD * DD];
__device__ __half g_yh[BB * LL * DD];
__device__ __half g_qh[BB * NH * LL * HD];
__device__ __half g_kh[BB * NKV * LL * HD];
__device__ __half g_vh[BB * NKV * LL * HD];
__device__ int    g_lo[BB * LL];
__device__ float4 g_rope[LL * 16];

// ---------------- ptx helpers ----------------
__device__ __forceinline__ uint32_t smem_u32(const void* p) {
    uint32_t a;
    asm("{ .reg .u64 t; cvta.to.shared.u64 t, %1; cvt.u32.u64 %0, t; }"
        : "=r"(a) : "l"(p));
    return a;
}
__device__ __forceinline__ void cp16(uint32_t smem_dst, const void* gsrc) {
    asm volatile("cp.async.cg.shared.global [%0], [%1], 16;\n"
                 :: "r"(smem_dst), "l"(gsrc));
}
__device__ __forceinline__ void cp_commit() {
    asm volatile("cp.async.commit_group;\n");
}
template <int N>
__device__ __forceinline__ void cp_wait() {
    asm volatile("cp.async.wait_group %0;\n" :: "n"(N));
}
__device__ __forceinline__ void ldsm4(uint32_t* r, uint32_t addr) {
    asm volatile("ldmatrix.sync.aligned.m8n8.x4.shared.b16 {%0,%1,%2,%3}, [%4];"
                 : "=r"(r[0]), "=r"(r[1]), "=r"(r[2]), "=r"(r[3]) : "r"(addr));
}
__device__ __forceinline__ void ldsm4t(uint32_t* r, uint32_t addr) {
    asm volatile("ldmatrix.sync.aligned.m8n8.x4.trans.shared.b16 {%0,%1,%2,%3}, [%4];"
                 : "=r"(r[0]), "=r"(r[1]), "=r"(r[2]), "=r"(r[3]) : "r"(addr));
}
__device__ __forceinline__ void mma_f16(float* c, const uint32_t* a, const uint32_t* b) {
    asm volatile(
        "mma.sync.aligned.m16n8k16.row.col.f32.f16.f16.f32 "
        "{%0,%1,%2,%3}, {%4,%5,%6,%7}, {%8,%9}, {%0,%1,%2,%3};"
        : "+f"(c[0]), "+f"(c[1]), "+f"(c[2]), "+f"(c[3])
        : "r"(a[0]), "r"(a[1]), "r"(a[2]), "r"(a[3]), "r"(b[0]), "r"(b[1]));
}

// ---------------- fused prep kernel ----------------
// seg | rope table | w_qkv conv | warp-per-row rmsnorm (w_out conv moved to attn launch)
#define NB_SEG  BB
#define NB_ROPE 128
#define NB_CONV 1536
#define NB_RMS  (BB * LL / 8)
#define NB_TOT  (NB_SEG + NB_ROPE + NB_CONV + NB_RMS)

__global__ void __launch_bounds__(256) prep_kernel(
    const float* __restrict__ x, const float* __restrict__ wq,
    const void* __restrict__ mask)
{
    const int bid = blockIdx.x;
    const int t = threadIdx.x;

    if (bid < NB_SEG) {
        __shared__ int sA[256];
        __shared__ int sB[256];
        __shared__ int encs;
        const int b = bid;
        if (t == 0) {
            const unsigned* mi = (const unsigned*)mask;
            int e = 0;
            for (int i = 0; i < 64; i++) {
                unsigned v = mi[i];
                if (v == 0x3F800000u) { e = 2; break; }
                if (v > 1u) e = 1;
            }
            encs = e;
        }
        __syncthreads();
        const int e = encs;

        int pref[8];
        int run = 0;
        const int base = t * 8;
#pragma unroll
        for (int i = 0; i < 8; i++) {
            const int idx = base + i;
            int mset;
            if (e == 0)      mset = ((const int*)mask)[b * LL + idx] != 0;
            else if (e == 1) mset = ((const unsigned char*)mask)[b * LL + idx] != 0;
            else             mset = ((const float*)mask)[b * LL + idx] != 0.0f;
            run = max(run, mset ? idx : 0);
            pref[i] = run;
        }
        sA[t] = run;
        __syncthreads();
        int* s = sA;
        int* d = sB;
        for (int off = 1; off < 256; off <<= 1) {
            int v = s[t];
            if (t >= off) v = max(v, s[t - off]);
            d[t] = v;
            __syncthreads();
            int* tmp = s; s = d; d = tmp;
        }
        const int excl = (t > 0) ? s[t - 1] : 0;
#pragma unroll
        for (int i = 0; i < 8; i++) {
            const int idx = base + i;
            g_lo[b * LL + idx] = max(idx - (WIN - 1), max(excl, pref[i]));
        }
    } else if (bid < NB_SEG + NB_ROPE) {
        const int i = (bid - NB_SEG) * 256 + t;
        const int l = i >> 4;
        const int j = (i & 15) * 2;
        const float lg = logf(10000.0f) * (1.0f / 32.0f);
        const float f0 = expf(-lg * (float)j);
        const float f1 = expf(-lg * (float)(j + 1));
        float s0, c0, s1, c1;
        sincosf((float)l * f0, &s0, &c0);
        sincosf((float)l * f1, &s1, &c1);
        g_rope[i] = make_float4(c0, c1, s0, s1);
    } else if (bid < NB_SEG + NB_ROPE + NB_CONV) {
        // w_qkv fp32 -> fp16
        const int i = ((bid - NB_SEG - NB_ROPE) * 256 + t) * 4;
        float4 v = *(const float4*)(wq + i);
        *(__half2*)(g_wqkvh + i) = __floats2half2_rn(v.x, v.y);
        *(__half2*)(g_wqkvh + i + 2) = __floats2half2_rn(v.z, v.w);
    } else {
        // warp-per-row rmsnorm: 8 rows per block, no barriers
        const int row = (bid - (NB_SEG + NB_ROPE + NB_CONV)) * 8 + (t >> 5);
        const int lane = t & 31;
        const float4* xr = (const float4*)(x + (size_t)row * DD);
        float4 v[8];
        float ss = 0.f;
#pragma unroll
        for (int i = 0; i < 8; i++) {
            v[i] = xr[lane + i * 32];
            ss += v[i].x * v[i].x + v[i].y * v[i].y + v[i].z * v[i].z + v[i].w * v[i].w;
        }
#pragma unroll
        for (int m = 16; m; m >>= 1) ss += __shfl_xor_sync(0xffffffffu, ss, m);
        const float inv = rsqrtf(ss * (1.0f / DD) + EPSV);
        __half2* hr = (__half2*)(g_hh + (size_t)row * DD);
#pragma unroll
        for (int i = 0; i < 8; i++) {
            hr[(lane + i * 32) * 2] = __floats2half2_rn(v[i].x * inv, v[i].y * inv);
            hr[(lane + i * 32) * 2 + 1] = __floats2half2_rn(v[i].z * inv, v[i].w * inv);
        }
    }
}

// ---------------- fp16 mma.sync GEMM: 512 threads, 16 warps (4/SMSP) ----------------
// ROUND-10 VERIFIED CONFIG. 128x128 tile, BK=64, NSTG=4 (128KB smem, 1 CTA/SM).
#define NSTG 4
#define STG_B (128 * 128)
#define GSMEM (2 * NSTG * STG_B)

template <int EPI>
__global__ void __launch_bounds__(512) hgemm_kernel(
    const __half* __restrict__ A, const __half* __restrict__ W,
    const float* __restrict__ res, float* __restrict__ C,
    int M, int N, int K)
{
    extern __shared__ char smem[];
    const uint32_t sb = smem_u32(smem);
    const uint32_t Asm = sb;
    const uint32_t Bsm = sb + NSTG * STG_B;

    const int t = threadIdx.x;
    const int lane = t & 31;
    const int wid = t >> 5;
    const int wm = (wid & 3) * 32;
    const int wn = (wid >> 2) * 32;
    const int m0 = blockIdx.y * 128;
    const int n0 = blockIdx.x * 128;

    const int lrow = t >> 2;
    const int lcb0 = (t & 3) * 32;
    const int lswz = (lrow & 7) << 4;
    const char* Agb = (const char*)(A + (size_t)(m0 + lrow) * K);
    const char* Wgb = (const char*)(W + (size_t)(n0 + lrow) * K);
    const uint32_t arow = Asm + lrow * 128;
    const uint32_t brow = Bsm + lrow * 128;

    float acc[2][4][4];
#pragma unroll
    for (int i = 0; i < 2; i++)
#pragma unroll
        for (int j = 0; j < 4; j++)
#pragma unroll
            for (int r = 0; r < 4; r++) acc[i][j][r] = 0.f;

    const int grp = lane >> 3;
    const int li = lane & 7;
    uint32_t a_ro[2]; int a_sw[2];
    uint32_t b_ro[2]; int b_sw[2];
#pragma unroll
    for (int mi = 0; mi < 2; mi++) {
        const int r = wm + mi * 16 + li + (grp & 1) * 8;
        a_ro[mi] = r * 128;
        a_sw[mi] = (r & 7) << 4;
    }
#pragma unroll
    for (int nb = 0; nb < 2; nb++) {
        const int r = wn + nb * 16 + li + (grp >> 1) * 8;
        b_ro[nb] = r * 128;
        b_sw[nb] = (r & 7) << 4;
    }
    const int a_g16 = (grp >> 1) * 16;
    const int b_g16 = (grp & 1) * 16;

    const int nch = K >> 6;

#pragma unroll
    for (int s = 0; s < NSTG - 1; s++) {
#pragma unroll
        for (int i = 0; i < 2; i++) {
            const int cb = lcb0 + i * 16;
            cp16(arow + s * STG_B + (cb ^ lswz), Agb + s * 128 + cb);
            cp16(brow + s * STG_B + (cb ^ lswz), Wgb + s * 128 + cb);
        }
        cp_commit();
    }

    cp_wait<NSTG - 2>();
    __syncthreads();

    uint32_t af[2][2][4], bf[2][2][4];
#pragma unroll
    for (int mi = 0; mi < 2; mi++)
        ldsm4(af[0][mi], Asm + a_ro[mi] + (a_g16 ^ a_sw[mi]));
#pragma unroll
    for (int nb = 0; nb < 2; nb++)
        ldsm4(bf[0][nb], Bsm + b_ro[nb] + (b_g16 ^ b_sw[nb]));

    int buf = 0;
    for (int c = 0; c < nch; c++) {
        const uint32_t as = Asm + (c % NSTG) * STG_B;
        const uint32_t bs = Bsm + (c % NSTG) * STG_B;
        const uint32_t asn = Asm + ((c + 1) % NSTG) * STG_B;
        const uint32_t bsn = Bsm + ((c + 1) % NSTG) * STG_B;

#pragma unroll
        for (int ks = 0; ks < 4; ks++) {
            if (ks == 3) {
                cp_wait<NSTG - 2>();
                __syncthreads();
            }
            if (c < nch - 1 || ks < 3) {
                const uint32_t las = (ks < 3) ? as : asn;
                const uint32_t lbs = (ks < 3) ? bs : bsn;
                const int koff = ((ks + 1) & 3) * 32;
#pragma unroll
                for (int mi = 0; mi < 2; mi++)
                    ldsm4(af[buf ^ 1][mi], las + a_ro[mi] + ((koff + a_g16) ^ a_sw[mi]));
#pragma unroll
                for (int nb = 0; nb < 2; nb++)
                    ldsm4(bf[buf ^ 1][nb], lbs + b_ro[nb] + ((koff + b_g16) ^ b_sw[nb]));
            }
            if (ks == 0) {
                const int pf = c + NSTG - 1;
                if (pf < nch) {
                    const int s = pf % NSTG;
#pragma unroll
                    for (int i = 0; i < 2; i++) {
                        const int cb = lcb0 + i * 16;
                        cp16(arow + s * STG_B + (cb ^ lswz), Agb + (size_t)pf * 128 + cb);
                        cp16(brow + s * STG_B + (cb ^ lswz), Wgb + (size_t)pf * 128 + cb);
                    }
                }
                cp_commit();
            }
#pragma unroll
            for (int mi = 0; mi < 2; mi++)
#pragma unroll
                for (int ni = 0; ni < 4; ni++)
                    mma_f16(acc[mi][ni], af[buf][mi], &bf[buf][ni >> 1][(ni & 1) * 2]);
            buf ^= 1;
        }
    }

    const int g = lane >> 2;
    const int tg = lane & 3;

    if (EPI == 1) {
#pragma unroll
        for (int mi = 0; mi < 2; mi++) {
#pragma unroll
            for (int ni = 0; ni < 4; ni++) {
                const int row = m0 + wm + mi * 16 + g;
                const int col = n0 + wn + ni * 8 + tg * 2;
                float2 v0 = make_float2(acc[mi][ni][0], acc[mi][ni][1]);
                float2 v1 = make_float2(acc[mi][ni][2], acc[mi][ni][3]);
                const float2 r0 = *(const float2*)(res + (size_t)row * N + col);
                const float2 r1 = *(const float2*)(res + (size_t)(row + 8) * N + col);
                v0.x += r0.x; v0.y += r0.y;
                v1.x += r1.x; v1.y += r1.y;
                *(float2*)(C + (size_t)row * N + col) = v0;
                *(float2*)(C + (size_t)(row + 8) * N + col) = v1;
            }
        }
    } else {
        __syncthreads();
        float* sf = (float*)smem;  // [128][132]
#pragma unroll
        for (int mi = 0; mi < 2; mi++) {
#pragma unroll
            for (int ni = 0; ni < 4; ni++) {
                const int r = wm + mi * 16 + g;
                const int cl = wn + ni * 8 + tg * 2;
                *(float2*)&sf[r * 132 + cl] = make_float2(acc[mi][ni][0], acc[mi][ni][1]);
                *(float2*)&sf[(r + 8) * 132 + cl] = make_float2(acc[mi][ni][2], acc[mi][ni][3]);
            }
        }
        __syncthreads();

        const int gi = t >> 4;
        const int tl = t & 15;
        const int j = tl * 2;
        const int hbase = n0 >> 6;

        for (int it = 0; it < 8; it++) {
            const int p = it * 32 + gi;
            const int r = p >> 1;
            const int hh = p & 1;
            const int head = hbase + hh;
            const int rowg = m0 + r;
            const int b = rowg >> 11;
            const int l = rowg & (LL - 1);
            const float* sr = &sf[r * 132 + hh * 64];

            const float a0 = sr[j], a1 = sr[j + 1];
            const float b0 = sr[j + 32], b1 = sr[j + 33];

            if (head < 20) {
                float ss = a0 * a0 + a1 * a1 + b0 * b0 + b1 * b1;
#pragma unroll
                for (int m = 8; m; m >>= 1)
                    ss += __shfl_xor_sync(0xffffffffu, ss, m, 16);
                const float inv = rsqrtf(ss * (1.0f / HD) + EPSV);
                const float4 rp = g_rope[l * 16 + tl];
                const float a0n = a0 * inv, a1n = a1 * inv;
                const float b0n = b0 * inv, b1n = b1 * inv;
                const float o0 = a0n * rp.x - b0n * rp.z;
                const float o1 = a1n * rp.y - b1n * rp.w;
                const float o2 = a0n * rp.z + b0n * rp.x;
                const float o3 = a1n * rp.w + b1n * rp.y;
                if (head < 16) {
                    const float sc = 0.125f;
                    __half* dq = g_qh + (((size_t)(b * NH + head)) * LL + l) * HD;
                    *(__half2*)(dq + j) = __floats2half2_rn(o0 * sc, o1 * sc);
                    *(__half2*)(dq + j + 32) = __floats2half2_rn(o2 * sc, o3 * sc);
                } else {
                    __half* dk = g_kh + (((size_t)(b * NKV + (head - 16))) * LL + l) * HD;
                    *(__half2*)(dk + j) = __floats2half2_rn(o0, o1);
                    *(__half2*)(dk + j + 32) = __floats2half2_rn(o2, o3);
                }
            } else {
                __half* dv = g_vh + (((size_t)(b * NKV + (head - 20))) * LL + l) * HD;
                *(__half2*)(dv + j) = __floats2half2_rn(a0, a1);
                *(__half2*)(dv + j + 32) = __floats2half2_rn(b0, b1);
            }
        }
    }
}

// ---------------- tensor-core flash attention (round-10 verified) + w_out conv ----------------
// grid (32 + 32, 16, 2): qb<32 attention; qb>=32 convert w_out fp32->fp16.
#define ATT_SMEM (5 * 8192)
__global__ void __launch_bounds__(128) attn_mma_kernel(const float* __restrict__ wo) {
    const int qb = blockIdx.x, h = blockIdx.y, b = blockIdx.z;
    const int t = threadIdx.x;

    if (qb >= 32) {
        // ---- w_out conversion rider: 1024 blocks x 1024 floats ----
        const int cb = (qb - 32) + 32 * (h + NH * b);
        const int i = cb * 1024 + t * 8;
        const float4 v0 = *(const float4*)(wo + i);
        const float4 v1 = *(const float4*)(wo + i + 4);
        *(__half2*)(g_wouth + i) = __floats2half2_rn(v0.x, v0.y);
        *(__half2*)(g_wouth + i + 2) = __floats2half2_rn(v0.z, v0.w);
        *(__half2*)(g_wouth + i + 4) = __floats2half2_rn(v1.x, v1.y);
        *(__half2*)(g_wouth + i + 6) = __floats2half2_rn(v1.z, v1.w);
        return;
    }

    extern __shared__ char smc[];
    const uint32_t sb = smem_u32(smc);
    const uint32_t Qs = sb;
    const uint32_t Ks = sb + 8192;
    const uint32_t Vs = sb + 3 * 8192;
    __shared__ int lo_s[64];

    const int lane = t & 31;
    const int w = t >> 5;
    const int q0 = qb * 64;
    const int kvh = h >> 2;
    const char* Qg = (const char*)(g_qh + (((size_t)(b * NH + h)) * LL + q0) * HD);
    const char* Kg = (const char*)(g_kh + ((size_t)(b * NKV + kvh)) * LL * HD);
    const char* Vg = (const char*)(g_vh + ((size_t)(b * NKV + kvh)) * LL * HD);

    const int kb0 = g_lo[b * LL + q0] & ~63;
    const int nt = ((q0 + 63 - kb0) >> 6) + 1;
    if (t < 64) lo_s[t] = g_lo[b * LL + q0 + t];

    const int lrow = t >> 1;
    const int lcb0 = (t & 1) * 64;
    const int lswz = (lrow & 7) << 4;
    const uint32_t qrow_s = Qs + lrow * 128;
    const uint32_t krow_s = Ks + lrow * 128;
    const uint32_t vrow_s = Vs + lrow * 128;

#pragma unroll
    for (int i = 0; i < 4; i++) {
        const int cb = lcb0 + i * 16;
        cp16(qrow_s + (cb ^ lswz), Qg + lrow * 128 + cb);
        cp16(krow_s + (cb ^ lswz), Kg + (size_t)(kb0 + lrow) * 128 + cb);
        cp16(vrow_s + (cb ^ lswz), Vg + (size_t)(kb0 + lrow) * 128 + cb);
    }
    cp_commit();

    const int grp = lane >> 3;
    const int li = lane & 7;
    const int g = lane >> 2;
    const int tg = lane & 3;
    const int row0 = w * 16 + g;
    const int qg0 = q0 + row0;
    const int qg1 = qg0 + 8;

    cp_wait<0>();
    __syncthreads();

    uint32_t aQ[4][4];
    {
        const int qr = w * 16 + li + (grp & 1) * 8;
        const uint32_t qa = Qs + qr * 128;
        const int qsw = (qr & 7) << 4;
        const int qg16 = (grp >> 1) * 16;
#pragma unroll
        for (int kk = 0; kk < 4; kk++)
            ldsm4(aQ[kk], qa + ((kk * 32 + qg16) ^ qsw));
    }

    const int lo0 = lo_s[row0];
    const int lo1 = lo_s[row0 + 8];

    uint32_t k_ro[4]; int k_sw[4];
    uint32_t v_co[4];
#pragma unroll
    for (int nb = 0; nb < 4; nb++) {
        const int r = nb * 16 + li + (grp >> 1) * 8;
        k_ro[nb] = r * 128;
        k_sw[nb] = (r & 7) << 4;
        v_co[nb] = nb * 32 + (grp >> 1) * 16;
    }
    const int k_g16 = (grp & 1) * 16;
    const int v_r8 = (grp & 1) * 8 + li;

    float m0 = -1e30f, m1 = -1e30f, l0 = 0.f, l1 = 0.f;
    float o[8][4];
#pragma unroll
    for (int jn = 0; jn < 8; jn++)
#pragma unroll
        for (int r = 0; r < 4; r++) o[jn][r] = 0.f;

    for (int i = 0; i < nt; i++) {
        const int kb = kb0 + i * 64;
        if (i + 1 < nt) {
            const int bo = ((i + 1) & 1) * 8192;
            const size_t go = (size_t)(kb + 64 + lrow) * 128;
#pragma unroll
            for (int c2 = 0; c2 < 4; c2++) {
                const int cb = lcb0 + c2 * 16;
                cp16(krow_s + bo + (cb ^ lswz), Kg + go + cb);
                cp16(vrow_s + bo + (cb ^ lswz), Vg + go + cb);
            }
        }
        cp_commit();
        cp_wait<1>();
        __syncthreads();

        const uint32_t Kb = Ks + (i & 1) * 8192;
        const uint32_t Vb = Vs + (i & 1) * 8192;

        float sc[8][4];
#pragma unroll
        for (int j = 0; j < 8; j++)
#pragma unroll
            for (int r = 0; r < 4; r++) sc[j][r] = 0.f;

#pragma unroll
        for (int kk = 0; kk < 4; kk++) {
            uint32_t bfr[4][4];
#pragma unroll
            for (int nb = 0; nb < 4; nb++)
                ldsm4(bfr[nb], Kb + k_ro[nb] + ((kk * 32 + k_g16) ^ k_sw[nb]));
#pragma unroll
            for (int j = 0; j < 8; j++)
                mma_f16(sc[j], aQ[kk], &bfr[j >> 1][(j & 1) * 2]);
        }

        float mx0 = -1e30f, mx1 = -1e30f;
#pragma unroll
        for (int j = 0; j < 8; j++) {
            const int c0 = kb + j * 8 + tg * 2;
            const int c1 = c0 + 1;
            if (c0 < lo0 || c0 > qg0) sc[j][0] = -1e30f;
            if (c1 < lo0 || c1 > qg0) sc[j][1] = -1e30f;
            if (c0 < lo1 || c0 > qg1) sc[j][2] = -1e30f;
            if (c1 < lo1 || c1 > qg1) sc[j][3] = -1e30f;
            mx0 = fmaxf(mx0, fmaxf(sc[j][0], sc[j][1]));
            mx1 = fmaxf(mx1, fmaxf(sc[j][2], sc[j][3]));
        }
        mx0 = fmaxf(mx0, __shfl_xor_sync(0xffffffffu, mx0, 1));
        mx0 = fmaxf(mx0, __shfl_xor_sync(0xffffffffu, mx0, 2));
        mx1 = fmaxf(mx1, __shfl_xor_sync(0xffffffffu, mx1, 1));
        mx1 = fmaxf(mx1, __shfl_xor_sync(0xffffffffu, mx1, 2));

        const float mn0 = fmaxf(m0, mx0);
        const float mn1 = fmaxf(m1, mx1);
        const float al0 = __expf(m0 - mn0);
        const float al1 = __expf(m1 - mn1);

        float lp0 = 0.f, lp1 = 0.f;
        uint32_t ph[8][2];
#pragma unroll
        for (int j = 0; j < 8; j++) {
            const float p0 = (sc[j][0] > -1e29f) ? __expf(sc[j][0] - mn0) : 0.f;
            const float p1 = (sc[j][1] > -1e29f) ? __expf(sc[j][1] - mn0) : 0.f;
            const float p2 = (sc[j][2] > -1e29f) ? __expf(sc[j][2] - mn1) : 0.f;
            const float p3 = (sc[j][3] > -1e29f) ? __expf(sc[j][3] - mn1) : 0.f;
            lp0 += p0 + p1;
            lp1 += p2 + p3;
            __half2 h0 = __floats2half2_rn(p0, p1);
            __half2 h1 = __floats2half2_rn(p2, p3);
            ph[j][0] = *(uint32_t*)&h0;
            ph[j][1] = *(uint32_t*)&h1;
        }
        lp0 += __shfl_xor_sync(0xffffffffu, lp0, 1);
        lp0 += __shfl_xor_sync(0xffffffffu, lp0, 2);
        lp1 += __shfl_xor_sync(0xffffffffu, lp1, 1);
        lp1 += __shfl_xor_sync(0xffffffffu, lp1, 2);

        l0 = l0 * al0 + lp0;
        l1 = l1 * al1 + lp1;
        m0 = mn0; m1 = mn1;
#pragma unroll
        for (int jn = 0; jn < 8; jn++) {
            o[jn][0] *= al0; o[jn][1] *= al0;
            o[jn][2] *= al1; o[jn][3] *= al1;
        }

#pragma unroll
        for (int kk = 0; kk < 4; kk++) {
            uint32_t vf[4][4];
            const int vr = kk * 16 + v_r8;
            const uint32_t va = Vb + vr * 128;
            const int vsw = (vr & 7) << 4;
#pragma unroll
            for (int nb = 0; nb < 4; nb++)
                ldsm4t(vf[nb], va + (v_co[nb] ^ vsw));
            uint32_t aP[4] = { ph[2 * kk][0], ph[2 * kk][1],
                               ph[2 * kk + 1][0], ph[2 * kk + 1][1] };
#pragma unroll
            for (int jn = 0; jn < 8; jn++)
                mma_f16(o[jn], aP, &vf[jn >> 1][(jn & 1) * 2]);
        }
        __syncthreads();
    }

    const float iv0 = 1.0f / l0;
    const float iv1 = 1.0f / l1;
    __half* y0 = g_yh + ((size_t)(b * LL) + qg0) * DD + h * HD;
    __half* y1 = g_yh + ((size_t)(b * LL) + qg1) * DD + h * HD;
#pragma unroll
    for (int jn = 0; jn < 8; jn++) {
        __half2 r0 = __floats2half2_rn(o[jn][0] * iv0, o[jn][1] * iv0);
        __half2 r1 = __floats2half2_rn(o[jn][2] * iv1, o[jn][3] * iv1);
        *(__half2*)(y0 + jn * 8 + tg * 2) = r0;
        *(__half2*)(y1 + jn * 8 + tg * 2) = r1;
    }
}

// ---------------- launch ----------------
extern "C" void kernel_launch(void* const* d_in, const int* in_sizes, int n_in,
                              void* d_out, int out_size) {
    const float* x     = (const float*)d_in[0];
    const float* w_qkv = (const float*)d_in[1];
    const float* w_out = (const float*)d_in[2];
    const void*  mask  = d_in[3];
    float* out = (float*)d_out;

    __half *phh, *pwqh, *pwoh, *pyh;
    cudaGetSymbolAddress((void**)&phh, g_hh);
    cudaGetSymbolAddress((void**)&pwqh, g_wqkvh);
    cudaGetSymbolAddress((void**)&pwoh, g_wouth);
    cudaGetSymbolAddress((void**)&pyh, g_yh);

    const int M = BB * LL;

    cudaFuncSetAttribute(hgemm_kernel<1>,
                         cudaFuncAttributeMaxDynamicSharedMemorySize, GSMEM);
    cudaFuncSetAttribute(hgemm_kernel<2>,
                         cudaFuncAttributeMaxDynamicSharedMemorySize, GSMEM);
    cudaFuncSetAttribute(attn_mma_kernel,
                         cudaFuncAttributeMaxDynamicSharedMemorySize, ATT_SMEM);

    prep_kernel<<<NB_TOT, 256>>>(x, w_qkv, mask);

    hgemm_kernel<2><<<dim3(QKV_DIM / 128, M / 128), 512, GSMEM>>>(
        phh, pwqh, nullptr, nullptr, M, QKV_DIM, DD);

    attn_mma_kernel<<<dim3(64, NH, BB), 128, ATT_SMEM>>>(w_out);

    hgemm_kernel<1><<<dim3(DD / 128, M / 128), 512, GSMEM>>>(
        pyh, pwoh, x, out, M, DD, DD);
}